// round 1
// baseline (speedup 1.0000x reference)
#include <cuda_runtime.h>
#include <math.h>

// Problem constants (static from reference)
#define B_    4
#define LQ    4096
#define CC    768
#define NHH   12
#define DH    64
#define NPP   4
#define HH    64
#define WW    64
#define HID   192
#define MROWS (B_*LQ)   // 16384

// -------- scratch (alloc-free, module-static) --------
__device__ float g_ln   [MROWS*CC];    // LN output (reused 3x)
__device__ float g_value[MROWS*CC];    // value = LN(feat)@Wv+bv   [B, HW, NH*DH]
__device__ float g_samp [MROWS*CC];    // sampled attention output [B, Lq, NH*DH]
__device__ float g_off  [MROWS*96];    // offsets  [B, Lq, NH*NP*2]
__device__ float g_att  [MROWS*48];    // attn logits [B, Lq, NH*NP]
__device__ float g_h    [MROWS*HID];   // FFN hidden

// ================= LayerNorm: one block per row of 768 =================
__global__ __launch_bounds__(256) void ln_kernel(const float* __restrict__ in,
                                                 const float* __restrict__ gamma,
                                                 const float* __restrict__ beta,
                                                 float* __restrict__ out)
{
    int row = blockIdx.x;
    const float* x = in + (size_t)row * CC;
    int t = threadIdx.x;
    float v0 = x[t], v1 = x[t + 256], v2 = x[t + 512];
    float s  = v0 + v1 + v2;
    float s2 = v0*v0 + v1*v1 + v2*v2;
    #pragma unroll
    for (int o = 16; o; o >>= 1) {
        s  += __shfl_xor_sync(0xffffffffu, s,  o);
        s2 += __shfl_xor_sync(0xffffffffu, s2, o);
    }
    __shared__ float ssum[8], ssum2[8];
    int w = t >> 5;
    if ((t & 31) == 0) { ssum[w] = s; ssum2[w] = s2; }
    __syncthreads();
    float S = 0.f, S2 = 0.f;
    #pragma unroll
    for (int i = 0; i < 8; i++) { S += ssum[i]; S2 += ssum2[i]; }
    float mean = S * (1.0f / CC);
    float var  = S2 * (1.0f / CC) - mean * mean;
    float inv  = rsqrtf(var + 1e-5f);
    float* o = out + (size_t)row * CC;
    o[t]       = (v0 - mean) * inv * gamma[t]       + beta[t];
    o[t + 256] = (v1 - mean) * inv * gamma[t + 256] + beta[t + 256];
    o[t + 512] = (v2 - mean) * inv * gamma[t + 512] + beta[t + 512];
}

// ================= Tiled fp32 GEMM: C = A[M,K]@W[K,N] + bias (+res) (opt GELU) ==
// BM=BN=128, BK=16, 256 threads, 8x8 microtile. M fixed = 16384 (grid.y=128).
template<bool NALIGN, bool GELU>
__global__ __launch_bounds__(256) void gemm_kernel(
    const float* __restrict__ A, const float* __restrict__ W,
    const float* __restrict__ bias, const float* __restrict__ res,
    float* __restrict__ C, int N, int K)
{
    const int BM = 128, BN = 128, BK = 16;
    __shared__ float As[BK][BM];
    __shared__ float Bs[BK][BN];
    int m0 = blockIdx.y * BM, n0 = blockIdx.x * BN;
    int tid = threadIdx.x;
    int tx = tid & 15, ty = tid >> 4;

    float acc[8][8];
    #pragma unroll
    for (int i = 0; i < 8; i++)
        #pragma unroll
        for (int j = 0; j < 8; j++) acc[i][j] = 0.f;

    for (int k0 = 0; k0 < K; k0 += BK) {
        // load A tile (always aligned: K % 16 == 0, M % 128 == 0)
        #pragma unroll
        for (int i = 0; i < 2; i++) {
            int f = i * 256 + tid;
            int row = f >> 2, c4 = f & 3;
            float4 v = *reinterpret_cast<const float4*>(A + (size_t)(m0 + row) * K + k0 + c4 * 4);
            As[c4*4+0][row] = v.x; As[c4*4+1][row] = v.y;
            As[c4*4+2][row] = v.z; As[c4*4+3][row] = v.w;
        }
        // load B tile
        #pragma unroll
        for (int i = 0; i < 2; i++) {
            int f = i * 256 + tid;
            int kr = f >> 5, c4 = f & 31;
            int n = n0 + c4 * 4;
            if (NALIGN || n + 4 <= N) {
                float4 v = *reinterpret_cast<const float4*>(W + (size_t)(k0 + kr) * N + n);
                *reinterpret_cast<float4*>(&Bs[kr][c4*4]) = v;
            } else {
                Bs[kr][c4*4+0] = 0.f; Bs[kr][c4*4+1] = 0.f;
                Bs[kr][c4*4+2] = 0.f; Bs[kr][c4*4+3] = 0.f;
            }
        }
        __syncthreads();
        #pragma unroll
        for (int kk = 0; kk < BK; kk++) {
            const float4* a4 = reinterpret_cast<const float4*>(&As[kk][0]);
            const float4* b4 = reinterpret_cast<const float4*>(&Bs[kk][0]);
            float4 a0 = a4[ty*2], a1 = a4[ty*2+1];
            float4 b0 = b4[tx*2], b1 = b4[tx*2+1];
            float ar[8] = {a0.x,a0.y,a0.z,a0.w,a1.x,a1.y,a1.z,a1.w};
            float br[8] = {b0.x,b0.y,b0.z,b0.w,b1.x,b1.y,b1.z,b1.w};
            #pragma unroll
            for (int i = 0; i < 8; i++)
                #pragma unroll
                for (int j = 0; j < 8; j++)
                    acc[i][j] = fmaf(ar[i], br[j], acc[i][j]);
        }
        __syncthreads();
    }

    #pragma unroll
    for (int i = 0; i < 8; i++) {
        int m = m0 + ty * 8 + i;
        #pragma unroll
        for (int j = 0; j < 8; j++) {
            int n = n0 + tx * 8 + j;
            if (NALIGN || n < N) {
                float v = acc[i][j] + bias[n];
                if (res) v += res[(size_t)m * N + n];
                if (GELU) v = 0.5f * v * (1.0f + erff(v * 0.70710678118654752f));
                C[(size_t)m * N + n] = v;
            }
        }
    }
}

// ================= Sampling: softmax(4) + bilinear gather, per (b,q,head) ======
// 256 threads = 4 groups of 64; each group handles one (b,q,head), lanes = d.
__global__ __launch_bounds__(256) void sample_kernel(
    const float* __restrict__ value,   // [B, HW, NH*DH]
    const float* __restrict__ refp,    // [B, Lq, 1, 2]
    const float* __restrict__ off,     // [B, Lq, 96]
    const float* __restrict__ logits,  // [B, Lq, 48]
    float* __restrict__ out)           // [B, Lq, NH*DH]
{
    int gid = blockIdx.x * 4 + (threadIdx.x >> 6);   // over B*Lq*NH
    int di  = threadIdx.x & 63;
    int head = gid % NHH;
    int bq   = gid / NHH;             // b*Lq + q
    int b    = bq / LQ;

    const float* rp = refp + (size_t)bq * 2;
    float rx = rp[0], ry = rp[1];
    const float* op = off + (size_t)bq * 96 + head * 8;
    const float* lp = logits + (size_t)bq * 48 + head * 4;

    float l0 = lp[0], l1 = lp[1], l2 = lp[2], l3 = lp[3];
    float mx = fmaxf(fmaxf(l0, l1), fmaxf(l2, l3));
    float e0 = expf(l0 - mx), e1 = expf(l1 - mx), e2 = expf(l2 - mx), e3 = expf(l3 - mx);
    float inv = 1.0f / (e0 + e1 + e2 + e3);
    float wsm[4] = {e0 * inv, e1 * inv, e2 * inv, e3 * inv};

    const float* vb = value + (size_t)b * (HH * WW) * CC + head * DH + di;
    float acc = 0.f;
    #pragma unroll
    for (int p = 0; p < 4; p++) {
        // loc = ref + off/[W,H];  x = loc_x*W - 0.5 = rx*W + off_x - 0.5
        float x = rx * (float)WW + op[p*2+0] - 0.5f;
        float y = ry * (float)HH + op[p*2+1] - 0.5f;
        float x0f = floorf(x), y0f = floorf(y);
        int   x0 = (int)x0f,  y0 = (int)y0f;
        float wx1 = x - x0f, wy1 = y - y0f;
        float wx0 = 1.f - wx1, wy0 = 1.f - wy1;
        float s = 0.f;
        #pragma unroll
        for (int c = 0; c < 4; c++) {
            int xi = x0 + (c & 1);
            int yi = y0 + (c >> 1);
            float w = ((c & 1) ? wx1 : wx0) * ((c >> 1) ? wy1 : wy0);
            if (xi >= 0 && xi < WW && yi >= 0 && yi < HH)
                s += w * vb[(size_t)(yi * WW + xi) * CC];
        }
        acc += wsm[p] * s;
    }
    out[(size_t)bq * CC + head * DH + di] = acc;
}

// ======================= launch ========================
extern "C" void kernel_launch(void* const* d_in, const int* in_sizes, int n_in,
                              void* d_out, int out_size)
{
    const float* query = (const float*)d_in[0];
    const float* refp  = (const float*)d_in[1];
    const float* feat  = (const float*)d_in[2];
    int p = n_in - 18;   // robust to scalar H/W encoding
    const float* qn_g  = (const float*)d_in[p + 0];
    const float* qn_b  = (const float*)d_in[p + 1];
    const float* fn_g  = (const float*)d_in[p + 2];
    const float* fn_b  = (const float*)d_in[p + 3];
    const float* Wv    = (const float*)d_in[p + 4];
    const float* bv    = (const float*)d_in[p + 5];
    const float* Woff  = (const float*)d_in[p + 6];
    const float* boff  = (const float*)d_in[p + 7];
    const float* Watt  = (const float*)d_in[p + 8];
    const float* batt  = (const float*)d_in[p + 9];
    const float* Wout  = (const float*)d_in[p + 10];
    const float* bout  = (const float*)d_in[p + 11];
    const float* ffn_g = (const float*)d_in[p + 12];
    const float* ffn_b = (const float*)d_in[p + 13];
    const float* W1    = (const float*)d_in[p + 14];
    const float* b1    = (const float*)d_in[p + 15];
    const float* W2    = (const float*)d_in[p + 16];
    const float* b2    = (const float*)d_in[p + 17];
    float* out = (float*)d_out;

    float *s_ln, *s_value, *s_samp, *s_off, *s_att, *s_h;
    cudaGetSymbolAddress((void**)&s_ln,    g_ln);
    cudaGetSymbolAddress((void**)&s_value, g_value);
    cudaGetSymbolAddress((void**)&s_samp,  g_samp);
    cudaGetSymbolAddress((void**)&s_off,   g_off);
    cudaGetSymbolAddress((void**)&s_att,   g_att);
    cudaGetSymbolAddress((void**)&s_h,     g_h);

    // 1. value = LN(feat) @ Wv + bv
    ln_kernel<<<MROWS, 256>>>(feat, fn_g, fn_b, s_ln);
    gemm_kernel<true,  false><<<dim3(6, 128), 256>>>(s_ln, Wv, bv, nullptr, s_value, CC, CC);

    // 2. qn = LN(query); offsets + attention logits
    ln_kernel<<<MROWS, 256>>>(query, qn_g, qn_b, s_ln);
    gemm_kernel<false, false><<<dim3(1, 128), 256>>>(s_ln, Woff, boff, nullptr, s_off, 96, CC);
    gemm_kernel<false, false><<<dim3(1, 128), 256>>>(s_ln, Watt, batt, nullptr, s_att, 48, CC);

    // 3. softmax + bilinear sampling
    sample_kernel<<<MROWS * NHH / 4, 256>>>(s_value, refp, s_off, s_att, s_samp);

    // 4. out = query + samp @ Wout + bout
    gemm_kernel<true,  false><<<dim3(6, 128), 256>>>(s_samp, Wout, bout, query, out, CC, CC);

    // 5. FFN: out += GELU(LN(out)@W1+b1) @ W2 + b2
    ln_kernel<<<MROWS, 256>>>(out, ffn_g, ffn_b, s_ln);
    gemm_kernel<false, true ><<<dim3(2, 128), 256>>>(s_ln, W1, b1, nullptr, s_h, HID, CC);
    gemm_kernel<true,  false><<<dim3(6, 128), 256>>>(s_h, W2, b2, out, out, CC, HID);
}

// round 3
// speedup vs baseline: 1.4554x; 1.4554x over previous
#include <cuda_runtime.h>
#include <cuda_fp16.h>
#include <math.h>
#include <cstdint>

// Problem constants
#define B_    4
#define LQ    4096
#define CC    768
#define NHH   12
#define DH    64
#define HH    64
#define WW    64
#define HID   192
#define MROWS (B_*LQ)   // 16384

// ---------------- scratch ----------------
__device__ __align__(16) __half g_xh[MROWS*CC], g_xl[MROWS*CC];     // LN outputs hi/lo
__device__ __align__(16) float  g_value[MROWS*CC];                  // value fp32 (gather src)
__device__ __align__(16) float  g_offatt[MROWS*192];                // off(96)+logits(48)+pad
__device__ __align__(16) __half g_sh[MROWS*CC], g_sl[MROWS*CC];     // sampled hi/lo
__device__ __align__(16) __half g_hh[MROWS*HID], g_hl[MROWS*HID];   // FFN hidden hi/lo
// transposed+split weights [Npad][K]
__device__ __align__(16) __half g_wvt_h[CC*CC],  g_wvt_l[CC*CC];
__device__ __align__(16) __half g_wot_h[CC*CC],  g_wot_l[CC*CC];
__device__ __align__(16) __half g_wct_h[256*CC], g_wct_l[256*CC];
__device__ __align__(16) __half g_w1t_h[256*CC], g_w1t_l[256*CC];
__device__ __align__(16) __half g_w2t_h[CC*HID], g_w2t_l[CC*HID];
__device__ float g_bcomb[256], g_b1p[256];

// ---------------- weight transpose + fp16 split ----------------
__global__ void wsplit_kernel(const float* __restrict__ src, __half* __restrict__ hi,
                              __half* __restrict__ lo, int K, int N, int Npad)
{
    int idx = blockIdx.x * 256 + threadIdx.x;
    if (idx >= Npad * K) return;
    int n = idx / K, k = idx - n * K;
    float v = (n < N) ? src[(size_t)k * N + n] : 0.0f;
    __half h = __float2half(v);
    hi[idx] = h;
    lo[idx] = __float2half(v - __half2float(h));
}
__global__ void biasprep_kernel(const float* __restrict__ boff, const float* __restrict__ batt,
                                const float* __restrict__ b1, float* __restrict__ bcomb, float* __restrict__ b1p)
{
    int i = threadIdx.x;
    bcomb[i] = (i < 96) ? boff[i] : (i < 144 ? batt[i - 96] : 0.0f);
    b1p[i]   = (i < 192) ? b1[i] : 0.0f;
}

// ---------------- LayerNorm -> fp16 hi/lo ----------------
__global__ __launch_bounds__(256) void ln_split_kernel(const float* __restrict__ in,
                                                       const float* __restrict__ gamma,
                                                       const float* __restrict__ beta,
                                                       __half* __restrict__ oh,
                                                       __half* __restrict__ ol)
{
    int row = blockIdx.x;
    const float* x = in + (size_t)row * CC;
    int t = threadIdx.x;
    float v0 = x[t], v1 = x[t + 256], v2 = x[t + 512];
    float s  = v0 + v1 + v2;
    float s2 = v0*v0 + v1*v1 + v2*v2;
    #pragma unroll
    for (int o = 16; o; o >>= 1) {
        s  += __shfl_xor_sync(0xffffffffu, s,  o);
        s2 += __shfl_xor_sync(0xffffffffu, s2, o);
    }
    __shared__ float ssum[8], ssum2[8];
    int w = t >> 5;
    if ((t & 31) == 0) { ssum[w] = s; ssum2[w] = s2; }
    __syncthreads();
    float S = 0.f, S2 = 0.f;
    #pragma unroll
    for (int i = 0; i < 8; i++) { S += ssum[i]; S2 += ssum2[i]; }
    float mean = S * (1.0f / CC);
    float var  = S2 * (1.0f / CC) - mean * mean;
    float inv  = rsqrtf(var + 1e-5f);
    size_t base = (size_t)row * CC;
    #pragma unroll
    for (int i = 0; i < 3; i++) {
        int c = t + i * 256;
        float v = (i == 0 ? v0 : (i == 1 ? v1 : v2));
        float y = (v - mean) * inv * gamma[c] + beta[c];
        __half h = __float2half(y);
        oh[base + c] = h;
        ol[base + c] = __float2half(y - __half2float(h));
    }
}

// ---------------- mma.sync fp16-split GEMM ----------------
// C[M,N] = A[M,K] @ B^T, B stored [Npad][K]. 3-term error-compensated fp16 MMA.
// CTA 128x128, 8 warps (2 M x 4 N), each warp 64x32, BK=64.
// EPI: 0 bias->fp32; 1 bias+res->fp32; 2 bias+GELU->fp16 hi/lo.
#define SSTR 72  // smem row stride in halfs (64 + 8 pad)

__device__ __forceinline__ void mma16816(float* d, const uint32_t* a, const uint32_t* b) {
    asm volatile(
        "mma.sync.aligned.m16n8k16.row.col.f32.f16.f16.f32 "
        "{%0,%1,%2,%3}, {%4,%5,%6,%7}, {%8,%9}, {%0,%1,%2,%3};"
        : "+f"(d[0]), "+f"(d[1]), "+f"(d[2]), "+f"(d[3])
        : "r"(a[0]), "r"(a[1]), "r"(a[2]), "r"(a[3]), "r"(b[0]), "r"(b[1]));
}

template<int EPI>
__global__ __launch_bounds__(256, 2) void mma_gemm(
    const __half* __restrict__ Ahi, const __half* __restrict__ Alo,
    const __half* __restrict__ Bhi, const __half* __restrict__ Blo,
    const float* __restrict__ bias, const float* __restrict__ res,
    float* __restrict__ Cf, __half* __restrict__ Chi, __half* __restrict__ Clo,
    int K, int ldc, int Ncols)
{
    extern __shared__ __half sm[];
    __half* sAH = sm;
    __half* sAL = sm + 128 * SSTR;
    __half* sBH = sm + 2 * 128 * SSTR;
    __half* sBL = sm + 3 * 128 * SSTR;

    const int tid = threadIdx.x, lane = tid & 31, wid = tid >> 5;
    const int wm = wid & 1, wn = wid >> 1;           // warp grid 2x4
    const int m0 = blockIdx.y * 128, n0 = blockIdx.x * 128;

    float acc[4][4][4];
    #pragma unroll
    for (int i = 0; i < 4; i++)
        #pragma unroll
        for (int j = 0; j < 4; j++)
            #pragma unroll
            for (int q = 0; q < 4; q++) acc[i][j][q] = 0.f;

    const int qrow = lane >> 2, qk = (lane & 3) * 2;

    for (int kc = 0; kc < K; kc += 64) {
        // ---- stage tiles ----
        #pragma unroll
        for (int i = 0; i < 4; i++) {
            int idx = i * 256 + tid;          // 0..1023
            int row = idx >> 3, g = idx & 7;  // row 0..127, 8-half group
            size_t ga = (size_t)(m0 + row) * K + kc + g * 8;
            size_t gb = (size_t)(n0 + row) * K + kc + g * 8;
            int so = row * SSTR + g * 8;
            *reinterpret_cast<float4*>(sAH + so) = *reinterpret_cast<const float4*>(Ahi + ga);
            *reinterpret_cast<float4*>(sAL + so) = *reinterpret_cast<const float4*>(Alo + ga);
            *reinterpret_cast<float4*>(sBH + so) = *reinterpret_cast<const float4*>(Bhi + gb);
            *reinterpret_cast<float4*>(sBL + so) = *reinterpret_cast<const float4*>(Blo + gb);
        }
        __syncthreads();

        #pragma unroll
        for (int kk = 0; kk < 4; kk++) {
            const int kb = kk * 16;
            uint32_t bh[4][2], bl[4][2];
            #pragma unroll
            for (int ni = 0; ni < 4; ni++) {
                int brow = wn * 32 + ni * 8 + qrow;
                int bc = kb + qk;
                bh[ni][0] = *reinterpret_cast<const uint32_t*>(sBH + brow * SSTR + bc);
                bh[ni][1] = *reinterpret_cast<const uint32_t*>(sBH + brow * SSTR + bc + 8);
                bl[ni][0] = *reinterpret_cast<const uint32_t*>(sBL + brow * SSTR + bc);
                bl[ni][1] = *reinterpret_cast<const uint32_t*>(sBL + brow * SSTR + bc + 8);
            }
            #pragma unroll
            for (int mi = 0; mi < 4; mi++) {
                int arow = wm * 64 + mi * 16 + qrow;
                int ac = kb + qk;
                uint32_t ah[4], al[4];
                ah[0] = *reinterpret_cast<const uint32_t*>(sAH + arow * SSTR + ac);
                ah[1] = *reinterpret_cast<const uint32_t*>(sAH + (arow + 8) * SSTR + ac);
                ah[2] = *reinterpret_cast<const uint32_t*>(sAH + arow * SSTR + ac + 8);
                ah[3] = *reinterpret_cast<const uint32_t*>(sAH + (arow + 8) * SSTR + ac + 8);
                al[0] = *reinterpret_cast<const uint32_t*>(sAL + arow * SSTR + ac);
                al[1] = *reinterpret_cast<const uint32_t*>(sAL + (arow + 8) * SSTR + ac);
                al[2] = *reinterpret_cast<const uint32_t*>(sAL + arow * SSTR + ac + 8);
                al[3] = *reinterpret_cast<const uint32_t*>(sAL + (arow + 8) * SSTR + ac + 8);
                #pragma unroll
                for (int ni = 0; ni < 4; ni++) {
                    mma16816(acc[mi][ni], ah, bh[ni]);
                    mma16816(acc[mi][ni], ah, bl[ni]);
                    mma16816(acc[mi][ni], al, bh[ni]);
                }
            }
        }
        __syncthreads();
    }

    // ---- epilogue ----
    #pragma unroll
    for (int mi = 0; mi < 4; mi++) {
        #pragma unroll
        for (int ni = 0; ni < 4; ni++) {
            int r0 = m0 + wm * 64 + mi * 16 + qrow;
            int c0 = n0 + wn * 32 + ni * 8 + qk;
            #pragma unroll
            for (int q = 0; q < 4; q++) {
                int m = r0 + (q >> 1) * 8;
                int n = c0 + (q & 1);
                if (n < Ncols) {
                    float v = acc[mi][ni][q] + bias[n];
                    if (EPI == 1) v += res[(size_t)m * ldc + n];
                    if (EPI == 2) {
                        v = 0.5f * v * (1.0f + erff(v * 0.70710678118654752f));
                        __half h = __float2half(v);
                        Chi[(size_t)m * ldc + n] = h;
                        Clo[(size_t)m * ldc + n] = __float2half(v - __half2float(h));
                    } else {
                        Cf[(size_t)m * ldc + n] = v;
                    }
                }
            }
        }
    }
}

// ---------------- sampling: softmax(4) + bilinear -> fp16 hi/lo ----------------
__global__ __launch_bounds__(256) void sample_kernel(
    const float* __restrict__ value,    // [B, HW, 768]
    const float* __restrict__ refp,     // [B, Lq, 1, 2]
    const float* __restrict__ offatt,   // [B*Lq, 192]
    __half* __restrict__ oh, __half* __restrict__ ol)
{
    int gid = blockIdx.x * 4 + (threadIdx.x >> 6);
    int di  = threadIdx.x & 63;
    int head = gid % NHH;
    int bq   = gid / NHH;
    int b    = bq / LQ;

    const float* rp = refp + (size_t)bq * 2;
    float rx = rp[0], ry = rp[1];
    const float* op = offatt + (size_t)bq * 192 + head * 8;
    const float* lp = offatt + (size_t)bq * 192 + 96 + head * 4;

    float l0 = lp[0], l1 = lp[1], l2 = lp[2], l3 = lp[3];
    float mx = fmaxf(fmaxf(l0, l1), fmaxf(l2, l3));
    float e0 = expf(l0 - mx), e1 = expf(l1 - mx), e2 = expf(l2 - mx), e3 = expf(l3 - mx);
    float inv = 1.0f / (e0 + e1 + e2 + e3);
    float wsm[4] = {e0 * inv, e1 * inv, e2 * inv, e3 * inv};

    const float* vb = value + (size_t)b * (HH * WW) * CC + head * DH + di;
    float acc = 0.f;
    #pragma unroll
    for (int p = 0; p < 4; p++) {
        float x = rx * (float)WW + op[p*2+0] - 0.5f;
        float y = ry * (float)HH + op[p*2+1] - 0.5f;
        float x0f = floorf(x), y0f = floorf(y);
        int   x0 = (int)x0f,  y0 = (int)y0f;
        float wx1 = x - x0f, wy1 = y - y0f;
        float wx0 = 1.f - wx1, wy0 = 1.f - wy1;
        float s = 0.f;
        #pragma unroll
        for (int cc = 0; cc < 4; cc++) {
            int xi = x0 + (cc & 1);
            int yi = y0 + (cc >> 1);
            float w = ((cc & 1) ? wx1 : wx0) * ((cc >> 1) ? wy1 : wy0);
            if (xi >= 0 && xi < WW && yi >= 0 && yi < HH)
                s += w * vb[(size_t)(yi * WW + xi) * CC];
        }
        acc += wsm[p] * s;
    }
    size_t o = (size_t)bq * CC + head * DH + di;
    __half h = __float2half(acc);
    oh[o] = h;
    ol[o] = __float2half(acc - __half2float(h));
}

// ---------------- launch ----------------
extern "C" void kernel_launch(void* const* d_in, const int* in_sizes, int n_in,
                              void* d_out, int out_size)
{
    const float* query = (const float*)d_in[0];
    const float* refp  = (const float*)d_in[1];
    const float* feat  = (const float*)d_in[2];
    int p = n_in - 18;
    const float* qn_g  = (const float*)d_in[p + 0];
    const float* qn_b  = (const float*)d_in[p + 1];
    const float* fn_g  = (const float*)d_in[p + 2];
    const float* fn_b  = (const float*)d_in[p + 3];
    const float* Wv    = (const float*)d_in[p + 4];
    const float* bv    = (const float*)d_in[p + 5];
    const float* Woff  = (const float*)d_in[p + 6];
    const float* boff  = (const float*)d_in[p + 7];
    const float* Watt  = (const float*)d_in[p + 8];
    const float* batt  = (const float*)d_in[p + 9];
    const float* Wout  = (const float*)d_in[p + 10];
    const float* bout  = (const float*)d_in[p + 11];
    const float* ffn_g = (const float*)d_in[p + 12];
    const float* ffn_b = (const float*)d_in[p + 13];
    const float* W1    = (const float*)d_in[p + 14];
    const float* b1    = (const float*)d_in[p + 15];
    const float* W2    = (const float*)d_in[p + 16];
    const float* b2    = (const float*)d_in[p + 17];
    float* out = (float*)d_out;

    __half *xh, *xl, *sh, *sl, *hh, *hl;
    __half *wvh, *wvl, *woh, *wol, *wch, *wcl, *w1h, *w1l, *w2h, *w2l;
    float *valuef, *offatt, *bcomb, *b1p;
    cudaGetSymbolAddress((void**)&xh, g_xh);       cudaGetSymbolAddress((void**)&xl, g_xl);
    cudaGetSymbolAddress((void**)&sh, g_sh);       cudaGetSymbolAddress((void**)&sl, g_sl);
    cudaGetSymbolAddress((void**)&hh, g_hh);       cudaGetSymbolAddress((void**)&hl, g_hl);
    cudaGetSymbolAddress((void**)&wvh, g_wvt_h);   cudaGetSymbolAddress((void**)&wvl, g_wvt_l);
    cudaGetSymbolAddress((void**)&woh, g_wot_h);   cudaGetSymbolAddress((void**)&wol, g_wot_l);
    cudaGetSymbolAddress((void**)&wch, g_wct_h);   cudaGetSymbolAddress((void**)&wcl, g_wct_l);
    cudaGetSymbolAddress((void**)&w1h, g_w1t_h);   cudaGetSymbolAddress((void**)&w1l, g_w1t_l);
    cudaGetSymbolAddress((void**)&w2h, g_w2t_h);   cudaGetSymbolAddress((void**)&w2l, g_w2t_l);
    cudaGetSymbolAddress((void**)&valuef, g_value);
    cudaGetSymbolAddress((void**)&offatt, g_offatt);
    cudaGetSymbolAddress((void**)&bcomb, g_bcomb);
    cudaGetSymbolAddress((void**)&b1p, g_b1p);

    const int SMEM_GEMM = 4 * 128 * SSTR * 2;   // 73728 B
    cudaFuncSetAttribute(mma_gemm<0>, cudaFuncAttributeMaxDynamicSharedMemorySize, SMEM_GEMM);
    cudaFuncSetAttribute(mma_gemm<1>, cudaFuncAttributeMaxDynamicSharedMemorySize, SMEM_GEMM);
    cudaFuncSetAttribute(mma_gemm<2>, cudaFuncAttributeMaxDynamicSharedMemorySize, SMEM_GEMM);

    // weight prep
    wsplit_kernel<<<(CC*CC + 255)/256, 256>>>(Wv,   wvh, wvl, CC, CC, CC);
    wsplit_kernel<<<(CC*CC + 255)/256, 256>>>(Wout, woh, wol, CC, CC, CC);
    wsplit_kernel<<<(96*CC + 255)/256, 256>>>(Woff, wch, wcl, CC, 96, 96);
    wsplit_kernel<<<(160*CC + 255)/256, 256>>>(Watt, wch + 96*CC, wcl + 96*CC, CC, 48, 160);
    wsplit_kernel<<<(256*CC + 255)/256, 256>>>(W1,  w1h, w1l, CC, HID, 256);
    wsplit_kernel<<<(CC*HID + 255)/256, 256>>>(W2,  w2h, w2l, HID, CC, CC);
    biasprep_kernel<<<1, 256>>>(boff, batt, b1, bcomb, b1p);

    // 1. value = LN(feat) @ Wv + bv
    ln_split_kernel<<<MROWS, 256>>>(feat, fn_g, fn_b, xh, xl);
    mma_gemm<0><<<dim3(6, 128), 256, SMEM_GEMM>>>(xh, xl, wvh, wvl, bv, nullptr,
        valuef, nullptr, nullptr, CC, CC, CC);

    // 2. qn = LN(query); offsets + logits (combined)
    ln_split_kernel<<<MROWS, 256>>>(query, qn_g, qn_b, xh, xl);
    mma_gemm<0><<<dim3(2, 128), 256, SMEM_GEMM>>>(xh, xl, wch, wcl, bcomb, nullptr,
        offatt, nullptr, nullptr, CC, 192, 144);

    // 3. softmax + bilinear sampling
    sample_kernel<<<MROWS * NHH / 4, 256>>>(valuef, refp, offatt, sh, sl);

    // 4. out = query + samp @ Wout + bout
    mma_gemm<1><<<dim3(6, 128), 256, SMEM_GEMM>>>(sh, sl, woh, wol, bout, query,
        out, nullptr, nullptr, CC, CC, CC);

    // 5. FFN
    ln_split_kernel<<<MROWS, 256>>>(out, ffn_g, ffn_b, xh, xl);
    mma_gemm<2><<<dim3(2, 128), 256, SMEM_GEMM>>>(xh, xl, w1h, w1l, b1p, nullptr,
        nullptr, hh, hl, CC, HID, HID);
    mma_gemm<1><<<dim3(6, 128), 256, SMEM_GEMM>>>(hh, hl, w2h, w2l, b2, out,
        out, nullptr, nullptr, HID, CC, CC);
}

// round 4
// speedup vs baseline: 2.0816x; 1.4303x over previous
#include <cuda_runtime.h>
#include <cuda_fp16.h>
#include <math.h>
#include <cstdint>

// Problem constants
#define B_    4
#define LQ    4096
#define CC    768
#define NHH   12
#define DH    64
#define HH    64
#define WW    64
#define HID   192
#define MROWS (B_*LQ)   // 16384

// ---------------- scratch ----------------
__device__ __align__(16) __half g_xh[MROWS*CC], g_xl[MROWS*CC];     // LN outputs hi/lo
__device__ __align__(16) float  g_value[MROWS*CC];                  // value fp32 (gather src)
__device__ __align__(16) float  g_offatt[MROWS*192];                // off(96)+logits(48)+pad
__device__ __align__(16) __half g_sh[MROWS*CC], g_sl[MROWS*CC];     // sampled hi/lo
__device__ __align__(16) __half g_hh[MROWS*HID], g_hl[MROWS*HID];   // FFN hidden hi/lo
// transposed+split weights [Npad][K]
__device__ __align__(16) __half g_wvt_h[CC*CC],  g_wvt_l[CC*CC];
__device__ __align__(16) __half g_wot_h[CC*CC],  g_wot_l[CC*CC];
__device__ __align__(16) __half g_wct_h[256*CC], g_wct_l[256*CC];
__device__ __align__(16) __half g_w1t_h[256*CC], g_w1t_l[256*CC];
__device__ __align__(16) __half g_w2t_h[CC*HID], g_w2t_l[CC*HID];
__device__ float g_bcomb[256], g_b1p[256];

// ---------------- weight transpose + fp16 split ----------------
__global__ void wsplit_kernel(const float* __restrict__ src, __half* __restrict__ hi,
                              __half* __restrict__ lo, int K, int N, int Npad)
{
    int idx = blockIdx.x * 256 + threadIdx.x;
    if (idx >= Npad * K) return;
    int n = idx / K, k = idx - n * K;
    float v = (n < N) ? src[(size_t)k * N + n] : 0.0f;
    __half h = __float2half(v);
    hi[idx] = h;
    lo[idx] = __float2half(v - __half2float(h));
}
__global__ void biasprep_kernel(const float* __restrict__ boff, const float* __restrict__ batt,
                                const float* __restrict__ b1, float* __restrict__ bcomb, float* __restrict__ b1p)
{
    int i = threadIdx.x;
    bcomb[i] = (i < 96) ? boff[i] : (i < 144 ? batt[i - 96] : 0.0f);
    b1p[i]   = (i < 192) ? b1[i] : 0.0f;
}

// ---------------- LayerNorm -> fp16 hi/lo ----------------
__global__ __launch_bounds__(256) void ln_split_kernel(const float* __restrict__ in,
                                                       const float* __restrict__ gamma,
                                                       const float* __restrict__ beta,
                                                       __half* __restrict__ oh,
                                                       __half* __restrict__ ol)
{
    int row = blockIdx.x;
    const float* x = in + (size_t)row * CC;
    int t = threadIdx.x;
    float v0 = x[t], v1 = x[t + 256], v2 = x[t + 512];
    float s  = v0 + v1 + v2;
    float s2 = v0*v0 + v1*v1 + v2*v2;
    #pragma unroll
    for (int o = 16; o; o >>= 1) {
        s  += __shfl_xor_sync(0xffffffffu, s,  o);
        s2 += __shfl_xor_sync(0xffffffffu, s2, o);
    }
    __shared__ float ssum[8], ssum2[8];
    int w = t >> 5;
    if ((t & 31) == 0) { ssum[w] = s; ssum2[w] = s2; }
    __syncthreads();
    float S = 0.f, S2 = 0.f;
    #pragma unroll
    for (int i = 0; i < 8; i++) { S += ssum[i]; S2 += ssum2[i]; }
    float mean = S * (1.0f / CC);
    float var  = S2 * (1.0f / CC) - mean * mean;
    float inv  = rsqrtf(var + 1e-5f);
    size_t base = (size_t)row * CC;
    #pragma unroll
    for (int i = 0; i < 3; i++) {
        int c = t + i * 256;
        float v = (i == 0 ? v0 : (i == 1 ? v1 : v2));
        float y = (v - mean) * inv * gamma[c] + beta[c];
        __half h = __float2half(y);
        oh[base + c] = h;
        ol[base + c] = __float2half(y - __half2float(h));
    }
}

// ---------------- mma.sync fp16-split GEMM (ldmatrix + cp.async pipeline) ------
// C[M,N] = A[M,K] @ B^T, B stored [Npad][K]. 3-term error-compensated fp16 MMA.
// CTA 128x128, 8 warps (2 M x 4 N), warp tile 64x32, BK=64, 2-stage cp.async.
#define SSTR 72  // smem row stride in halfs (64 + 8 pad)

__device__ __forceinline__ void mma16816(float* d, const uint32_t* a, const uint32_t* b) {
    asm volatile(
        "mma.sync.aligned.m16n8k16.row.col.f32.f16.f16.f32 "
        "{%0,%1,%2,%3}, {%4,%5,%6,%7}, {%8,%9}, {%0,%1,%2,%3};"
        : "+f"(d[0]), "+f"(d[1]), "+f"(d[2]), "+f"(d[3])
        : "r"(a[0]), "r"(a[1]), "r"(a[2]), "r"(a[3]), "r"(b[0]), "r"(b[1]));
}
#define LDSM_X4(R0,R1,R2,R3,ADDR) \
    asm volatile("ldmatrix.sync.aligned.m8n8.x4.shared.b16 {%0,%1,%2,%3}, [%4];" \
        : "=r"(R0), "=r"(R1), "=r"(R2), "=r"(R3) : "r"(ADDR))
#define CPA16(DST,SRC) \
    asm volatile("cp.async.cg.shared.global [%0], [%1], 16;" :: "r"(DST), "l"(SRC) : "memory")
#define CPC() asm volatile("cp.async.commit_group;" ::: "memory")
#define CPW1() asm volatile("cp.async.wait_group 1;" ::: "memory")

template<int EPI>
__global__ __launch_bounds__(256) void mma_gemm(
    const __half* __restrict__ Ahi, const __half* __restrict__ Alo,
    const __half* __restrict__ Bhi, const __half* __restrict__ Blo,
    const float* __restrict__ bias, const float* __restrict__ res,
    float* __restrict__ Cf, __half* __restrict__ Chi, __half* __restrict__ Clo,
    int K, int ldc, int Ncols)
{
    extern __shared__ __half sm[];
    const int ARR = 128 * SSTR;        // halves per array
    const int STG = 4 * ARR;           // halves per stage (AH, AL, BH, BL)

    const int tid = threadIdx.x, lane = tid & 31, wid = tid >> 5;
    const int wm = wid & 1, wn = wid >> 1;           // warp grid 2x4
    const int m0 = blockIdx.y * 128, n0 = blockIdx.x * 128;

    const uint32_t smb = (uint32_t)__cvta_generic_to_shared(sm);

    // per-thread staging coords: 1024 16B-chunks per array, 256 threads, 4 iters
    int srow[4], sg[4];
    #pragma unroll
    for (int i = 0; i < 4; i++) { int idx = i * 256 + tid; srow[i] = idx >> 3; sg[i] = idx & 7; }

    // issue async loads of K-chunk c into stage s
    auto issue = [&](int c, int s) {
        const int kc = c * 64;
        #pragma unroll
        for (int i = 0; i < 4; i++) {
            int row = srow[i], g = sg[i];
            size_t ga = (size_t)(m0 + row) * K + kc + g * 8;
            size_t gb = (size_t)(n0 + row) * K + kc + g * 8;
            uint32_t so = smb + (uint32_t)(s * STG + row * SSTR + g * 8) * 2;
            CPA16(so + 0 * ARR * 2, Ahi + ga);
            CPA16(so + 1 * ARR * 2, Alo + ga);
            CPA16(so + 2 * ARR * 2, Bhi + gb);
            CPA16(so + 3 * ARR * 2, Blo + gb);
        }
    };

    float acc[4][4][4];
    #pragma unroll
    for (int i = 0; i < 4; i++)
        #pragma unroll
        for (int j = 0; j < 4; j++)
            #pragma unroll
            for (int q = 0; q < 4; q++) acc[i][j][q] = 0.f;

    // ldmatrix per-lane base offsets (in halves)
    const int a_lrow = lane & 15, a_lcol = (lane >> 4) * 8;
    const int b_lrow = (lane & 7) + ((lane >> 4) * 8), b_lcol = ((lane >> 3) & 1) * 8;

    const int KC = K >> 6;
    issue(0, 0); CPC();

    for (int c = 0; c < KC; c++) {
        if (c + 1 < KC) { issue(c + 1, (c + 1) & 1); }
        CPC();
        CPW1();
        __syncthreads();

        const int st = (c & 1) * STG;
        const uint32_t baseAH = smb + (uint32_t)(st + 0 * ARR) * 2;
        const uint32_t baseAL = smb + (uint32_t)(st + 1 * ARR) * 2;
        const uint32_t baseBH = smb + (uint32_t)(st + 2 * ARR) * 2;
        const uint32_t baseBL = smb + (uint32_t)(st + 3 * ARR) * 2;

        #pragma unroll
        for (int kk = 0; kk < 4; kk++) {
            const int kb = kk * 16;
            uint32_t bh[4][2], bl[4][2];
            #pragma unroll
            for (int nn = 0; nn < 2; nn++) {
                uint32_t off = (uint32_t)((wn * 32 + nn * 16 + b_lrow) * SSTR + kb + b_lcol) * 2;
                LDSM_X4(bh[nn*2][0], bh[nn*2][1], bh[nn*2+1][0], bh[nn*2+1][1], baseBH + off);
                LDSM_X4(bl[nn*2][0], bl[nn*2][1], bl[nn*2+1][0], bl[nn*2+1][1], baseBL + off);
            }
            #pragma unroll
            for (int mi = 0; mi < 4; mi++) {
                uint32_t off = (uint32_t)((wm * 64 + mi * 16 + a_lrow) * SSTR + kb + a_lcol) * 2;
                uint32_t ah[4], al[4];
                LDSM_X4(ah[0], ah[1], ah[2], ah[3], baseAH + off);
                LDSM_X4(al[0], al[1], al[2], al[3], baseAL + off);
                #pragma unroll
                for (int ni = 0; ni < 4; ni++) {
                    mma16816(acc[mi][ni], ah, bh[ni]);
                    mma16816(acc[mi][ni], ah, bl[ni]);
                    mma16816(acc[mi][ni], al, bh[ni]);
                }
            }
        }
        __syncthreads();
    }

    // ---- epilogue ----
    const int qrow = lane >> 2, qk = (lane & 3) * 2;
    #pragma unroll
    for (int mi = 0; mi < 4; mi++) {
        #pragma unroll
        for (int ni = 0; ni < 4; ni++) {
            int r0 = m0 + wm * 64 + mi * 16 + qrow;
            int c0 = n0 + wn * 32 + ni * 8 + qk;
            #pragma unroll
            for (int q = 0; q < 4; q++) {
                int m = r0 + (q >> 1) * 8;
                int n = c0 + (q & 1);
                if (n < Ncols) {
                    float v = acc[mi][ni][q] + bias[n];
                    if (EPI == 1) v += res[(size_t)m * ldc + n];
                    if (EPI == 2) {
                        v = 0.5f * v * (1.0f + erff(v * 0.70710678118654752f));
                        __half h = __float2half(v);
                        Chi[(size_t)m * ldc + n] = h;
                        Clo[(size_t)m * ldc + n] = __float2half(v - __half2float(h));
                    } else {
                        Cf[(size_t)m * ldc + n] = v;
                    }
                }
            }
        }
    }
}

// ---------------- sampling: softmax(4) + bilinear -> fp16 hi/lo ----------------
__global__ __launch_bounds__(256) void sample_kernel(
    const float* __restrict__ value,    // [B, HW, 768]
    const float* __restrict__ refp,     // [B, Lq, 1, 2]
    const float* __restrict__ offatt,   // [B*Lq, 192]
    __half* __restrict__ oh, __half* __restrict__ ol)
{
    int gid = blockIdx.x * 4 + (threadIdx.x >> 6);
    int di  = threadIdx.x & 63;
    int head = gid % NHH;
    int bq   = gid / NHH;
    int b    = bq / LQ;

    const float* rp = refp + (size_t)bq * 2;
    float rx = rp[0], ry = rp[1];
    const float* op = offatt + (size_t)bq * 192 + head * 8;
    const float* lp = offatt + (size_t)bq * 192 + 96 + head * 4;

    float l0 = lp[0], l1 = lp[1], l2 = lp[2], l3 = lp[3];
    float mx = fmaxf(fmaxf(l0, l1), fmaxf(l2, l3));
    float e0 = expf(l0 - mx), e1 = expf(l1 - mx), e2 = expf(l2 - mx), e3 = expf(l3 - mx);
    float inv = 1.0f / (e0 + e1 + e2 + e3);
    float wsm[4] = {e0 * inv, e1 * inv, e2 * inv, e3 * inv};

    const float* vb = value + (size_t)b * (HH * WW) * CC + head * DH + di;
    float acc = 0.f;
    #pragma unroll
    for (int p = 0; p < 4; p++) {
        float x = rx * (float)WW + op[p*2+0] - 0.5f;
        float y = ry * (float)HH + op[p*2+1] - 0.5f;
        float x0f = floorf(x), y0f = floorf(y);
        int   x0 = (int)x0f,  y0 = (int)y0f;
        float wx1 = x - x0f, wy1 = y - y0f;
        float wx0 = 1.f - wx1, wy0 = 1.f - wy1;
        float s = 0.f;
        #pragma unroll
        for (int cc = 0; cc < 4; cc++) {
            int xi = x0 + (cc & 1);
            int yi = y0 + (cc >> 1);
            float w = ((cc & 1) ? wx1 : wx0) * ((cc >> 1) ? wy1 : wy0);
            if (xi >= 0 && xi < WW && yi >= 0 && yi < HH)
                s += w * vb[(size_t)(yi * WW + xi) * CC];
        }
        acc += wsm[p] * s;
    }
    size_t o = (size_t)bq * CC + head * DH + di;
    __half h = __float2half(acc);
    oh[o] = h;
    ol[o] = __float2half(acc - __half2float(h));
}

// ---------------- launch ----------------
extern "C" void kernel_launch(void* const* d_in, const int* in_sizes, int n_in,
                              void* d_out, int out_size)
{
    const float* query = (const float*)d_in[0];
    const float* refp  = (const float*)d_in[1];
    const float* feat  = (const float*)d_in[2];
    int p = n_in - 18;
    const float* qn_g  = (const float*)d_in[p + 0];
    const float* qn_b  = (const float*)d_in[p + 1];
    const float* fn_g  = (const float*)d_in[p + 2];
    const float* fn_b  = (const float*)d_in[p + 3];
    const float* Wv    = (const float*)d_in[p + 4];
    const float* bv    = (const float*)d_in[p + 5];
    const float* Woff  = (const float*)d_in[p + 6];
    const float* boff  = (const float*)d_in[p + 7];
    const float* Watt  = (const float*)d_in[p + 8];
    const float* batt  = (const float*)d_in[p + 9];
    const float* Wout  = (const float*)d_in[p + 10];
    const float* bout  = (const float*)d_in[p + 11];
    const float* ffn_g = (const float*)d_in[p + 12];
    const float* ffn_b = (const float*)d_in[p + 13];
    const float* W1    = (const float*)d_in[p + 14];
    const float* b1    = (const float*)d_in[p + 15];
    const float* W2    = (const float*)d_in[p + 16];
    const float* b2    = (const float*)d_in[p + 17];
    float* out = (float*)d_out;

    __half *xh, *xl, *sh, *sl, *hh, *hl;
    __half *wvh, *wvl, *woh, *wol, *wch, *wcl, *w1h, *w1l, *w2h, *w2l;
    float *valuef, *offatt, *bcomb, *b1p;
    cudaGetSymbolAddress((void**)&xh, g_xh);       cudaGetSymbolAddress((void**)&xl, g_xl);
    cudaGetSymbolAddress((void**)&sh, g_sh);       cudaGetSymbolAddress((void**)&sl, g_sl);
    cudaGetSymbolAddress((void**)&hh, g_hh);       cudaGetSymbolAddress((void**)&hl, g_hl);
    cudaGetSymbolAddress((void**)&wvh, g_wvt_h);   cudaGetSymbolAddress((void**)&wvl, g_wvt_l);
    cudaGetSymbolAddress((void**)&woh, g_wot_h);   cudaGetSymbolAddress((void**)&wol, g_wot_l);
    cudaGetSymbolAddress((void**)&wch, g_wct_h);   cudaGetSymbolAddress((void**)&wcl, g_wct_l);
    cudaGetSymbolAddress((void**)&w1h, g_w1t_h);   cudaGetSymbolAddress((void**)&w1l, g_w1t_l);
    cudaGetSymbolAddress((void**)&w2h, g_w2t_h);   cudaGetSymbolAddress((void**)&w2l, g_w2t_l);
    cudaGetSymbolAddress((void**)&valuef, g_value);
    cudaGetSymbolAddress((void**)&offatt, g_offatt);
    cudaGetSymbolAddress((void**)&bcomb, g_bcomb);
    cudaGetSymbolAddress((void**)&b1p, g_b1p);

    const int SMEM_GEMM = 2 * 4 * 128 * SSTR * 2;   // 147456 B (2-stage pipeline)
    cudaFuncSetAttribute(mma_gemm<0>, cudaFuncAttributeMaxDynamicSharedMemorySize, SMEM_GEMM);
    cudaFuncSetAttribute(mma_gemm<1>, cudaFuncAttributeMaxDynamicSharedMemorySize, SMEM_GEMM);
    cudaFuncSetAttribute(mma_gemm<2>, cudaFuncAttributeMaxDynamicSharedMemorySize, SMEM_GEMM);

    // weight prep
    wsplit_kernel<<<(CC*CC + 255)/256, 256>>>(Wv,   wvh, wvl, CC, CC, CC);
    wsplit_kernel<<<(CC*CC + 255)/256, 256>>>(Wout, woh, wol, CC, CC, CC);
    wsplit_kernel<<<(96*CC + 255)/256, 256>>>(Woff, wch, wcl, CC, 96, 96);
    wsplit_kernel<<<(160*CC + 255)/256, 256>>>(Watt, wch + 96*CC, wcl + 96*CC, CC, 48, 160);
    wsplit_kernel<<<(256*CC + 255)/256, 256>>>(W1,  w1h, w1l, CC, HID, 256);
    wsplit_kernel<<<(CC*HID + 255)/256, 256>>>(W2,  w2h, w2l, HID, CC, CC);
    biasprep_kernel<<<1, 256>>>(boff, batt, b1, bcomb, b1p);

    // 1. value = LN(feat) @ Wv + bv
    ln_split_kernel<<<MROWS, 256>>>(feat, fn_g, fn_b, xh, xl);
    mma_gemm<0><<<dim3(6, 128), 256, SMEM_GEMM>>>(xh, xl, wvh, wvl, bv, nullptr,
        valuef, nullptr, nullptr, CC, CC, CC);

    // 2. qn = LN(query); offsets + logits (combined)
    ln_split_kernel<<<MROWS, 256>>>(query, qn_g, qn_b, xh, xl);
    mma_gemm<0><<<dim3(2, 128), 256, SMEM_GEMM>>>(xh, xl, wch, wcl, bcomb, nullptr,
        offatt, nullptr, nullptr, CC, 192, 144);

    // 3. softmax + bilinear sampling
    sample_kernel<<<MROWS * NHH / 4, 256>>>(valuef, refp, offatt, sh, sl);

    // 4. out = query + samp @ Wout + bout
    mma_gemm<1><<<dim3(6, 128), 256, SMEM_GEMM>>>(sh, sl, woh, wol, bout, query,
        out, nullptr, nullptr, CC, CC, CC);

    // 5. FFN
    ln_split_kernel<<<MROWS, 256>>>(out, ffn_g, ffn_b, xh, xl);
    mma_gemm<2><<<dim3(2, 128), 256, SMEM_GEMM>>>(xh, xl, w1h, w1l, b1p, nullptr,
        nullptr, hh, hl, CC, HID, HID);
    mma_gemm<1><<<dim3(6, 128), 256, SMEM_GEMM>>>(hh, hl, w2h, w2l, b2, out,
        out, nullptr, nullptr, HID, CC, CC);
}

// round 5
// speedup vs baseline: 2.7243x; 1.3088x over previous
#include <cuda_runtime.h>
#include <cuda_fp16.h>
#include <math.h>
#include <cstdint>

// Problem constants
#define B_    4
#define LQ    4096
#define CC    768
#define NHH   12
#define DH    64
#define HH    64
#define WW    64
#define HID   192
#define MROWS (B_*LQ)   // 16384

// ---------------- scratch ----------------
__device__ __align__(16) __half g_x[MROWS*CC];                      // LN output (fp16)
__device__ __align__(16) __half g_value[MROWS*CC];                  // value fp16 (gather src)
__device__ __align__(16) float  g_offatt[MROWS*192];                // off(96)+logits(48)+pad
__device__ __align__(16) __half g_s[MROWS*CC];                      // sampled fp16
__device__ __align__(16) __half g_hmid[MROWS*HID];                  // FFN hidden fp16
// transposed+split weights [Npad][K] (hi/lo)
__device__ __align__(16) __half g_wvt_h[CC*CC],  g_wvt_l[CC*CC];
__device__ __align__(16) __half g_wot_h[CC*CC],  g_wot_l[CC*CC];
__device__ __align__(16) __half g_wct_h[256*CC], g_wct_l[256*CC];
__device__ __align__(16) __half g_w1t_h[256*CC], g_w1t_l[256*CC];
__device__ __align__(16) __half g_w2t_h[CC*HID], g_w2t_l[CC*HID];
__device__ float g_bcomb[256], g_b1p[256];

// ---------------- weight transpose + fp16 split ----------------
__global__ void wsplit_kernel(const float* __restrict__ src, __half* __restrict__ hi,
                              __half* __restrict__ lo, int K, int N, int Npad)
{
    int idx = blockIdx.x * 256 + threadIdx.x;
    if (idx >= Npad * K) return;
    int n = idx / K, k = idx - n * K;
    float v = (n < N) ? src[(size_t)k * N + n] : 0.0f;
    __half h = __float2half(v);
    hi[idx] = h;
    lo[idx] = __float2half(v - __half2float(h));
}
__global__ void biasprep_kernel(const float* __restrict__ boff, const float* __restrict__ batt,
                                const float* __restrict__ b1, float* __restrict__ bcomb, float* __restrict__ b1p)
{
    int i = threadIdx.x;
    bcomb[i] = (i < 96) ? boff[i] : (i < 144 ? batt[i - 96] : 0.0f);
    b1p[i]   = (i < 192) ? b1[i] : 0.0f;
}

// ---------------- LayerNorm -> fp16 ----------------
__global__ __launch_bounds__(256) void ln_half_kernel(const float* __restrict__ in,
                                                      const float* __restrict__ gamma,
                                                      const float* __restrict__ beta,
                                                      __half* __restrict__ oh)
{
    int row = blockIdx.x;
    const float* x = in + (size_t)row * CC;
    int t = threadIdx.x;
    float v0 = x[t], v1 = x[t + 256], v2 = x[t + 512];
    float s  = v0 + v1 + v2;
    float s2 = v0*v0 + v1*v1 + v2*v2;
    #pragma unroll
    for (int o = 16; o; o >>= 1) {
        s  += __shfl_xor_sync(0xffffffffu, s,  o);
        s2 += __shfl_xor_sync(0xffffffffu, s2, o);
    }
    __shared__ float ssum[8], ssum2[8];
    int w = t >> 5;
    if ((t & 31) == 0) { ssum[w] = s; ssum2[w] = s2; }
    __syncthreads();
    float S = 0.f, S2 = 0.f;
    #pragma unroll
    for (int i = 0; i < 8; i++) { S += ssum[i]; S2 += ssum2[i]; }
    float mean = S * (1.0f / CC);
    float var  = S2 * (1.0f / CC) - mean * mean;
    float inv  = rsqrtf(var + 1e-5f);
    size_t base = (size_t)row * CC;
    #pragma unroll
    for (int i = 0; i < 3; i++) {
        int c = t + i * 256;
        float v = (i == 0 ? v0 : (i == 1 ? v1 : v2));
        oh[base + c] = __float2half((v - mean) * inv * gamma[c] + beta[c]);
    }
}

// ---------------- mma.sync GEMM: A fp16, B hi/lo (2-term), cp.async 2-stage ----
// C[M,N] = A[M,K] @ B^T, B stored [Npad][K]. CTA 128x128, 8 warps 64x32, BK=64.
#define SSTR 72  // smem row stride in halfs

__device__ __forceinline__ void mma16816(float* d, const uint32_t* a, const uint32_t* b) {
    asm volatile(
        "mma.sync.aligned.m16n8k16.row.col.f32.f16.f16.f32 "
        "{%0,%1,%2,%3}, {%4,%5,%6,%7}, {%8,%9}, {%0,%1,%2,%3};"
        : "+f"(d[0]), "+f"(d[1]), "+f"(d[2]), "+f"(d[3])
        : "r"(a[0]), "r"(a[1]), "r"(a[2]), "r"(a[3]), "r"(b[0]), "r"(b[1]));
}
#define LDSM_X4(R0,R1,R2,R3,ADDR) \
    asm volatile("ldmatrix.sync.aligned.m8n8.x4.shared.b16 {%0,%1,%2,%3}, [%4];" \
        : "=r"(R0), "=r"(R1), "=r"(R2), "=r"(R3) : "r"(ADDR))
#define CPA16(DST,SRC) \
    asm volatile("cp.async.cg.shared.global [%0], [%1], 16;" :: "r"(DST), "l"(SRC) : "memory")
#define CPC() asm volatile("cp.async.commit_group;" ::: "memory")
#define CPW1() asm volatile("cp.async.wait_group 1;" ::: "memory")

// EPI: 0 bias->fp32; 1 bias+res->fp32; 2 bias+GELU->fp16; 3 bias->fp16
template<int EPI>
__global__ __launch_bounds__(256) void mma_gemm(
    const __half* __restrict__ A,
    const __half* __restrict__ Bhi, const __half* __restrict__ Blo,
    const float* __restrict__ bias, const float* __restrict__ res,
    float* __restrict__ Cf, __half* __restrict__ Ch,
    int K, int ldc, int Ncols)
{
    extern __shared__ __half sm[];
    const int ARR = 128 * SSTR;        // halves per array
    const int STG = 3 * ARR;           // stage: A, BH, BL

    const int tid = threadIdx.x, lane = tid & 31, wid = tid >> 5;
    const int wm = wid & 1, wn = wid >> 1;           // warp grid 2x4
    const int m0 = blockIdx.y * 128, n0 = blockIdx.x * 128;

    const uint32_t smb = (uint32_t)__cvta_generic_to_shared(sm);

    int srow[4], sg[4];
    #pragma unroll
    for (int i = 0; i < 4; i++) { int idx = i * 256 + tid; srow[i] = idx >> 3; sg[i] = idx & 7; }

    auto issue = [&](int c, int s) {
        const int kc = c * 64;
        #pragma unroll
        for (int i = 0; i < 4; i++) {
            int row = srow[i], g = sg[i];
            size_t ga = (size_t)(m0 + row) * K + kc + g * 8;
            size_t gb = (size_t)(n0 + row) * K + kc + g * 8;
            uint32_t so = smb + (uint32_t)(s * STG + row * SSTR + g * 8) * 2;
            CPA16(so + 0 * ARR * 2, A + ga);
            CPA16(so + 1 * ARR * 2, Bhi + gb);
            CPA16(so + 2 * ARR * 2, Blo + gb);
        }
    };

    float acc[4][4][4];
    #pragma unroll
    for (int i = 0; i < 4; i++)
        #pragma unroll
        for (int j = 0; j < 4; j++)
            #pragma unroll
            for (int q = 0; q < 4; q++) acc[i][j][q] = 0.f;

    const int a_lrow = lane & 15, a_lcol = (lane >> 4) * 8;
    const int b_lrow = (lane & 7) + ((lane >> 4) * 8), b_lcol = ((lane >> 3) & 1) * 8;

    const int KC = K >> 6;
    issue(0, 0); CPC();

    for (int c = 0; c < KC; c++) {
        if (c + 1 < KC) { issue(c + 1, (c + 1) & 1); }
        CPC();
        CPW1();
        __syncthreads();

        const int st = (c & 1) * STG;
        const uint32_t baseA  = smb + (uint32_t)(st + 0 * ARR) * 2;
        const uint32_t baseBH = smb + (uint32_t)(st + 1 * ARR) * 2;
        const uint32_t baseBL = smb + (uint32_t)(st + 2 * ARR) * 2;

        #pragma unroll
        for (int kk = 0; kk < 4; kk++) {
            const int kb = kk * 16;
            uint32_t bh[4][2], bl[4][2];
            #pragma unroll
            for (int nn = 0; nn < 2; nn++) {
                uint32_t off = (uint32_t)((wn * 32 + nn * 16 + b_lrow) * SSTR + kb + b_lcol) * 2;
                LDSM_X4(bh[nn*2][0], bh[nn*2][1], bh[nn*2+1][0], bh[nn*2+1][1], baseBH + off);
                LDSM_X4(bl[nn*2][0], bl[nn*2][1], bl[nn*2+1][0], bl[nn*2+1][1], baseBL + off);
            }
            #pragma unroll
            for (int mi = 0; mi < 4; mi++) {
                uint32_t off = (uint32_t)((wm * 64 + mi * 16 + a_lrow) * SSTR + kb + a_lcol) * 2;
                uint32_t ah[4];
                LDSM_X4(ah[0], ah[1], ah[2], ah[3], baseA + off);
                #pragma unroll
                for (int ni = 0; ni < 4; ni++) {
                    mma16816(acc[mi][ni], ah, bh[ni]);
                    mma16816(acc[mi][ni], ah, bl[ni]);
                }
            }
        }
        __syncthreads();
    }

    // ---- epilogue ----
    const int qrow = lane >> 2, qk = (lane & 3) * 2;
    #pragma unroll
    for (int mi = 0; mi < 4; mi++) {
        #pragma unroll
        for (int ni = 0; ni < 4; ni++) {
            int r0 = m0 + wm * 64 + mi * 16 + qrow;
            int c0 = n0 + wn * 32 + ni * 8 + qk;
            #pragma unroll
            for (int q = 0; q < 4; q++) {
                int m = r0 + (q >> 1) * 8;
                int n = c0 + (q & 1);
                if (n < Ncols) {
                    float v = acc[mi][ni][q] + bias[n];
                    if (EPI == 1) v += res[(size_t)m * ldc + n];
                    if (EPI == 2) {
                        v = 0.5f * v * (1.0f + erff(v * 0.70710678118654752f));
                        Ch[(size_t)m * ldc + n] = __float2half(v);
                    } else if (EPI == 3) {
                        Ch[(size_t)m * ldc + n] = __float2half(v);
                    } else {
                        Cf[(size_t)m * ldc + n] = v;
                    }
                }
            }
        }
    }
}

// ---------------- sampling: softmax(4) + bilinear -> fp16 ----------------
__global__ __launch_bounds__(256) void sample_kernel(
    const __half* __restrict__ value,   // [B, HW, 768] fp16
    const float* __restrict__ refp,     // [B, Lq, 1, 2]
    const float* __restrict__ offatt,   // [B*Lq, 192]
    __half* __restrict__ oh)
{
    int gid = blockIdx.x * 4 + (threadIdx.x >> 6);
    int di  = threadIdx.x & 63;
    int head = gid % NHH;
    int bq   = gid / NHH;
    int b    = bq / LQ;

    const float* rp = refp + (size_t)bq * 2;
    float rx = rp[0], ry = rp[1];
    const float* op = offatt + (size_t)bq * 192 + head * 8;
    const float* lp = offatt + (size_t)bq * 192 + 96 + head * 4;

    float l0 = lp[0], l1 = lp[1], l2 = lp[2], l3 = lp[3];
    float mx = fmaxf(fmaxf(l0, l1), fmaxf(l2, l3));
    float e0 = expf(l0 - mx), e1 = expf(l1 - mx), e2 = expf(l2 - mx), e3 = expf(l3 - mx);
    float inv = 1.0f / (e0 + e1 + e2 + e3);
    float wsm[4] = {e0 * inv, e1 * inv, e2 * inv, e3 * inv};

    const __half* vb = value + (size_t)b * (HH * WW) * CC + head * DH + di;
    float acc = 0.f;
    #pragma unroll
    for (int p = 0; p < 4; p++) {
        float x = rx * (float)WW + op[p*2+0] - 0.5f;
        float y = ry * (float)HH + op[p*2+1] - 0.5f;
        float x0f = floorf(x), y0f = floorf(y);
        int   x0 = (int)x0f,  y0 = (int)y0f;
        float wx1 = x - x0f, wy1 = y - y0f;
        float wx0 = 1.f - wx1, wy0 = 1.f - wy1;
        float s = 0.f;
        #pragma unroll
        for (int cc = 0; cc < 4; cc++) {
            int xi = x0 + (cc & 1);
            int yi = y0 + (cc >> 1);
            float w = ((cc & 1) ? wx1 : wx0) * ((cc >> 1) ? wy1 : wy0);
            if (xi >= 0 && xi < WW && yi >= 0 && yi < HH)
                s += w * __half2float(vb[(size_t)(yi * WW + xi) * CC]);
        }
        acc += wsm[p] * s;
    }
    oh[(size_t)bq * CC + head * DH + di] = __float2half(acc);
}

// ---------------- launch ----------------
extern "C" void kernel_launch(void* const* d_in, const int* in_sizes, int n_in,
                              void* d_out, int out_size)
{
    const float* query = (const float*)d_in[0];
    const float* refp  = (const float*)d_in[1];
    const float* feat  = (const float*)d_in[2];
    int p = n_in - 18;
    const float* qn_g  = (const float*)d_in[p + 0];
    const float* qn_b  = (const float*)d_in[p + 1];
    const float* fn_g  = (const float*)d_in[p + 2];
    const float* fn_b  = (const float*)d_in[p + 3];
    const float* Wv    = (const float*)d_in[p + 4];
    const float* bv    = (const float*)d_in[p + 5];
    const float* Woff  = (const float*)d_in[p + 6];
    const float* boff  = (const float*)d_in[p + 7];
    const float* Watt  = (const float*)d_in[p + 8];
    const float* batt  = (const float*)d_in[p + 9];
    const float* Wout  = (const float*)d_in[p + 10];
    const float* bout  = (const float*)d_in[p + 11];
    const float* ffn_g = (const float*)d_in[p + 12];
    const float* ffn_b = (const float*)d_in[p + 13];
    const float* W1    = (const float*)d_in[p + 14];
    const float* b1    = (const float*)d_in[p + 15];
    const float* W2    = (const float*)d_in[p + 16];
    const float* b2    = (const float*)d_in[p + 17];
    float* out = (float*)d_out;

    __half *x, *val, *s, *hmid;
    __half *wvh, *wvl, *woh, *wol, *wch, *wcl, *w1h, *w1l, *w2h, *w2l;
    float *offatt, *bcomb, *b1p;
    cudaGetSymbolAddress((void**)&x, g_x);
    cudaGetSymbolAddress((void**)&val, g_value);
    cudaGetSymbolAddress((void**)&s, g_s);
    cudaGetSymbolAddress((void**)&hmid, g_hmid);
    cudaGetSymbolAddress((void**)&wvh, g_wvt_h);   cudaGetSymbolAddress((void**)&wvl, g_wvt_l);
    cudaGetSymbolAddress((void**)&woh, g_wot_h);   cudaGetSymbolAddress((void**)&wol, g_wot_l);
    cudaGetSymbolAddress((void**)&wch, g_wct_h);   cudaGetSymbolAddress((void**)&wcl, g_wct_l);
    cudaGetSymbolAddress((void**)&w1h, g_w1t_h);   cudaGetSymbolAddress((void**)&w1l, g_w1t_l);
    cudaGetSymbolAddress((void**)&w2h, g_w2t_h);   cudaGetSymbolAddress((void**)&w2l, g_w2t_l);
    cudaGetSymbolAddress((void**)&offatt, g_offatt);
    cudaGetSymbolAddress((void**)&bcomb, g_bcomb);
    cudaGetSymbolAddress((void**)&b1p, g_b1p);

    const int SMEM_GEMM = 2 * 3 * 128 * SSTR * 2;   // 110592 B -> 2 CTAs/SM
    cudaFuncSetAttribute(mma_gemm<0>, cudaFuncAttributeMaxDynamicSharedMemorySize, SMEM_GEMM);
    cudaFuncSetAttribute(mma_gemm<1>, cudaFuncAttributeMaxDynamicSharedMemorySize, SMEM_GEMM);
    cudaFuncSetAttribute(mma_gemm<2>, cudaFuncAttributeMaxDynamicSharedMemorySize, SMEM_GEMM);
    cudaFuncSetAttribute(mma_gemm<3>, cudaFuncAttributeMaxDynamicSharedMemorySize, SMEM_GEMM);

    // weight prep
    wsplit_kernel<<<(CC*CC + 255)/256, 256>>>(Wv,   wvh, wvl, CC, CC, CC);
    wsplit_kernel<<<(CC*CC + 255)/256, 256>>>(Wout, woh, wol, CC, CC, CC);
    wsplit_kernel<<<(96*CC + 255)/256, 256>>>(Woff, wch, wcl, CC, 96, 96);
    wsplit_kernel<<<(160*CC + 255)/256, 256>>>(Watt, wch + 96*CC, wcl + 96*CC, CC, 48, 160);
    wsplit_kernel<<<(256*CC + 255)/256, 256>>>(W1,  w1h, w1l, CC, HID, 256);
    wsplit_kernel<<<(CC*HID + 255)/256, 256>>>(W2,  w2h, w2l, HID, CC, CC);
    biasprep_kernel<<<1, 256>>>(boff, batt, b1, bcomb, b1p);

    // 1. value = LN(feat) @ Wv + bv  -> fp16
    ln_half_kernel<<<MROWS, 256>>>(feat, fn_g, fn_b, x);
    mma_gemm<3><<<dim3(6, 128), 256, SMEM_GEMM>>>(x, wvh, wvl, bv, nullptr,
        nullptr, val, CC, CC, CC);

    // 2. qn = LN(query); offsets + logits
    ln_half_kernel<<<MROWS, 256>>>(query, qn_g, qn_b, x);
    mma_gemm<0><<<dim3(2, 128), 256, SMEM_GEMM>>>(x, wch, wcl, bcomb, nullptr,
        offatt, nullptr, CC, 192, 144);

    // 3. softmax + bilinear sampling -> fp16
    sample_kernel<<<MROWS * NHH / 4, 256>>>(val, refp, offatt, s);

    // 4. out = query + samp @ Wout + bout
    mma_gemm<1><<<dim3(6, 128), 256, SMEM_GEMM>>>(s, woh, wol, bout, query,
        out, nullptr, CC, CC, CC);

    // 5. FFN
    ln_half_kernel<<<MROWS, 256>>>(out, ffn_g, ffn_b, x);
    mma_gemm<2><<<dim3(2, 128), 256, SMEM_GEMM>>>(x, w1h, w1l, b1p, nullptr,
        nullptr, hmid, CC, HID, HID);
    mma_gemm<1><<<dim3(6, 128), 256, SMEM_GEMM>>>(hmid, w2h, w2l, b2, out,
        out, nullptr, HID, CC, CC);
}

// round 7
// speedup vs baseline: 3.4823x; 1.2782x over previous
#include <cuda_runtime.h>
#include <cuda_fp16.h>
#include <math.h>
#include <cstdint>

// Problem constants
#define B_    4
#define LQ    4096
#define CC    768
#define NHH   12
#define DH    64
#define HH    64
#define WW    64
#define HID   192
#define MROWS (B_*LQ)   // 16384

// ---------------- scratch ----------------
__device__ __align__(16) __half g_x[MROWS*CC];                      // LN output (fp16)
__device__ __align__(16) __half g_value[MROWS*CC];                  // value fp16 (gather src)
__device__ __align__(16) float  g_offatt[MROWS*192];                // off(96)+logits(48)+pad
__device__ __align__(16) __half g_s[MROWS*CC];                      // sampled fp16
__device__ __align__(16) __half g_hmid[MROWS*HID];                  // FFN hidden fp16
// transposed weights [Npad][K] fp16
__device__ __align__(16) __half g_wvt[CC*CC];
__device__ __align__(16) __half g_wot[CC*CC];
__device__ __align__(16) __half g_wct[256*CC];
__device__ __align__(16) __half g_w1t[256*CC];
__device__ __align__(16) __half g_w2t[CC*HID];
__device__ float g_bcomb[256], g_b1p[256];

// ---------------- weight transpose -> fp16 ----------------
__global__ void wtrans_kernel(const float* __restrict__ src, __half* __restrict__ dst,
                              int K, int N, int Npad)
{
    int idx = blockIdx.x * 256 + threadIdx.x;
    if (idx >= Npad * K) return;
    int n = idx / K, k = idx - n * K;
    float v = (n < N) ? src[(size_t)k * N + n] : 0.0f;
    dst[idx] = __float2half(v);
}
__global__ void biasprep_kernel(const float* __restrict__ boff, const float* __restrict__ batt,
                                const float* __restrict__ b1, float* __restrict__ bcomb, float* __restrict__ b1p)
{
    int i = threadIdx.x;
    bcomb[i] = (i < 96) ? boff[i] : (i < 144 ? batt[i - 96] : 0.0f);
    b1p[i]   = (i < 192) ? b1[i] : 0.0f;
}

// ---------------- LayerNorm -> fp16 ----------------
__global__ __launch_bounds__(256) void ln_half_kernel(const float* __restrict__ in,
                                                      const float* __restrict__ gamma,
                                                      const float* __restrict__ beta,
                                                      __half* __restrict__ oh)
{
    int row = blockIdx.x;
    const float* x = in + (size_t)row * CC;
    int t = threadIdx.x;
    float v0 = x[t], v1 = x[t + 256], v2 = x[t + 512];
    float s  = v0 + v1 + v2;
    float s2 = v0*v0 + v1*v1 + v2*v2;
    #pragma unroll
    for (int o = 16; o; o >>= 1) {
        s  += __shfl_xor_sync(0xffffffffu, s,  o);
        s2 += __shfl_xor_sync(0xffffffffu, s2, o);
    }
    __shared__ float ssum[8], ssum2[8];
    int w = t >> 5;
    if ((t & 31) == 0) { ssum[w] = s; ssum2[w] = s2; }
    __syncthreads();
    float S = 0.f, S2 = 0.f;
    #pragma unroll
    for (int i = 0; i < 8; i++) { S += ssum[i]; S2 += ssum2[i]; }
    float mean = S * (1.0f / CC);
    float var  = S2 * (1.0f / CC) - mean * mean;
    float inv  = rsqrtf(var + 1e-5f);
    size_t base = (size_t)row * CC;
    #pragma unroll
    for (int i = 0; i < 3; i++) {
        int c = t + i * 256;
        float v = (i == 0 ? v0 : (i == 1 ? v1 : v2));
        oh[base + c] = __float2half((v - mean) * inv * gamma[c] + beta[c]);
    }
}

// ---------------- mma.sync fp16 GEMM, cp.async 2-stage ----
// C[M,N] = A[M,K] @ B^T, B stored [Npad][K]. CTA 128x128, 8 warps 64x32, BK=64.
#define SSTR 72  // smem row stride in halfs

__device__ __forceinline__ void mma16816(float* d, const uint32_t* a, const uint32_t* b) {
    asm volatile(
        "mma.sync.aligned.m16n8k16.row.col.f32.f16.f16.f32 "
        "{%0,%1,%2,%3}, {%4,%5,%6,%7}, {%8,%9}, {%0,%1,%2,%3};"
        : "+f"(d[0]), "+f"(d[1]), "+f"(d[2]), "+f"(d[3])
        : "r"(a[0]), "r"(a[1]), "r"(a[2]), "r"(a[3]), "r"(b[0]), "r"(b[1]));
}
#define LDSM_X4(R0,R1,R2,R3,ADDR) \
    asm volatile("ldmatrix.sync.aligned.m8n8.x4.shared.b16 {%0,%1,%2,%3}, [%4];" \
        : "=r"(R0), "=r"(R1), "=r"(R2), "=r"(R3) : "r"(ADDR))
#define CPA16(DST,SRC) \
    asm volatile("cp.async.cg.shared.global [%0], [%1], 16;" :: "r"(DST), "l"(SRC) : "memory")
#define CPC() asm volatile("cp.async.commit_group;" ::: "memory")
#define CPW1() asm volatile("cp.async.wait_group 1;" ::: "memory")

// EPI: 0 bias->fp32; 1 bias+res->fp32; 2 bias+GELU->fp16; 3 bias->fp16
template<int EPI>
__global__ __launch_bounds__(256) void mma_gemm(
    const __half* __restrict__ A, const __half* __restrict__ B,
    const float* __restrict__ bias, const float* __restrict__ res,
    float* __restrict__ Cf, __half* __restrict__ Ch,
    int K, int ldc, int Ncols)
{
    extern __shared__ __half sm[];
    const int ARR = 128 * SSTR;        // halves per array
    const int STG = 2 * ARR;           // stage: A, B

    const int tid = threadIdx.x, lane = tid & 31, wid = tid >> 5;
    const int wm = wid & 1, wn = wid >> 1;           // warp grid 2x4
    const int m0 = blockIdx.y * 128, n0 = blockIdx.x * 128;

    const uint32_t smb = (uint32_t)__cvta_generic_to_shared(sm);

    int srow[4], sg[4];
    #pragma unroll
    for (int i = 0; i < 4; i++) { int idx = i * 256 + tid; srow[i] = idx >> 3; sg[i] = idx & 7; }

    auto issue = [&](int c, int s) {
        const int kc = c * 64;
        #pragma unroll
        for (int i = 0; i < 4; i++) {
            int row = srow[i], g = sg[i];
            size_t ga = (size_t)(m0 + row) * K + kc + g * 8;
            size_t gb = (size_t)(n0 + row) * K + kc + g * 8;
            uint32_t so = smb + (uint32_t)(s * STG + row * SSTR + g * 8) * 2;
            CPA16(so + 0 * ARR * 2, A + ga);
            CPA16(so + 1 * ARR * 2, B + gb);
        }
    };

    float acc[4][4][4];
    #pragma unroll
    for (int i = 0; i < 4; i++)
        #pragma unroll
        for (int j = 0; j < 4; j++)
            #pragma unroll
            for (int q = 0; q < 4; q++) acc[i][j][q] = 0.f;

    const int a_lrow = lane & 15, a_lcol = (lane >> 4) * 8;
    const int b_lrow = (lane & 7) + ((lane >> 4) * 8), b_lcol = ((lane >> 3) & 1) * 8;

    const int KC = K >> 6;
    issue(0, 0); CPC();

    for (int c = 0; c < KC; c++) {
        if (c + 1 < KC) { issue(c + 1, (c + 1) & 1); }
        CPC();
        CPW1();
        __syncthreads();

        const int st = (c & 1) * STG;
        const uint32_t baseA = smb + (uint32_t)(st + 0 * ARR) * 2;
        const uint32_t baseB = smb + (uint32_t)(st + 1 * ARR) * 2;

        #pragma unroll
        for (int kk = 0; kk < 4; kk++) {
            const int kb = kk * 16;
            uint32_t bf[4][2];
            #pragma unroll
            for (int nn = 0; nn < 2; nn++) {
                uint32_t off = (uint32_t)((wn * 32 + nn * 16 + b_lrow) * SSTR + kb + b_lcol) * 2;
                LDSM_X4(bf[nn*2][0], bf[nn*2][1], bf[nn*2+1][0], bf[nn*2+1][1], baseB + off);
            }
            #pragma unroll
            for (int mi = 0; mi < 4; mi++) {
                uint32_t off = (uint32_t)((wm * 64 + mi * 16 + a_lrow) * SSTR + kb + a_lcol) * 2;
                uint32_t ah[4];
                LDSM_X4(ah[0], ah[1], ah[2], ah[3], baseA + off);
                #pragma unroll
                for (int ni = 0; ni < 4; ni++)
                    mma16816(acc[mi][ni], ah, bf[ni]);
            }
        }
        __syncthreads();
    }

    // ---- epilogue ----
    const int qrow = lane >> 2, qk = (lane & 3) * 2;
    #pragma unroll
    for (int mi = 0; mi < 4; mi++) {
        #pragma unroll
        for (int ni = 0; ni < 4; ni++) {
            int r0 = m0 + wm * 64 + mi * 16 + qrow;
            int c0 = n0 + wn * 32 + ni * 8 + qk;
            #pragma unroll
            for (int q = 0; q < 4; q++) {
                int m = r0 + (q >> 1) * 8;
                int n = c0 + (q & 1);
                if (n < Ncols) {
                    float v = acc[mi][ni][q] + bias[n];
                    if (EPI == 1) v += res[(size_t)m * ldc + n];
                    if (EPI == 2) {
                        v = 0.5f * v * (1.0f + erff(v * 0.70710678118654752f));
                        Ch[(size_t)m * ldc + n] = __float2half(v);
                    } else if (EPI == 3) {
                        Ch[(size_t)m * ldc + n] = __float2half(v);
                    } else {
                        Cf[(size_t)m * ldc + n] = v;
                    }
                }
            }
        }
    }
}

// ---------------- sampling: softmax(4) + bilinear -> fp16 ----------------
__global__ __launch_bounds__(256) void sample_kernel(
    const __half* __restrict__ value,   // [B, HW, 768] fp16
    const float* __restrict__ refp,     // [B, Lq, 1, 2]
    const float* __restrict__ offatt,   // [B*Lq, 192]
    __half* __restrict__ oh)
{
    int gid = blockIdx.x * 4 + (threadIdx.x >> 6);
    int di  = threadIdx.x & 63;
    int head = gid % NHH;
    int bq   = gid / NHH;
    int b    = bq / LQ;

    const float* rp = refp + (size_t)bq * 2;
    float rx = rp[0], ry = rp[1];
    const float* op = offatt + (size_t)bq * 192 + head * 8;
    const float* lp = offatt + (size_t)bq * 192 + 96 + head * 4;

    float l0 = lp[0], l1 = lp[1], l2 = lp[2], l3 = lp[3];
    float mx = fmaxf(fmaxf(l0, l1), fmaxf(l2, l3));
    float e0 = expf(l0 - mx), e1 = expf(l1 - mx), e2 = expf(l2 - mx), e3 = expf(l3 - mx);
    float inv = 1.0f / (e0 + e1 + e2 + e3);
    float wsm[4] = {e0 * inv, e1 * inv, e2 * inv, e3 * inv};

    const __half* vb = value + (size_t)b * (HH * WW) * CC + head * DH + di;
    float acc = 0.f;
    #pragma unroll
    for (int p = 0; p < 4; p++) {
        float x = rx * (float)WW + op[p*2+0] - 0.5f;
        float y = ry * (float)HH + op[p*2+1] - 0.5f;
        float x0f = floorf(x), y0f = floorf(y);
        int   x0 = (int)x0f,  y0 = (int)y0f;
        float wx1 = x - x0f, wy1 = y - y0f;
        float wx0 = 1.f - wx1, wy0 = 1.f - wy1;
        float s = 0.f;
        #pragma unroll
        for (int cc = 0; cc < 4; cc++) {
            int xi = x0 + (cc & 1);
            int yi = y0 + (cc >> 1);
            float w = ((cc & 1) ? wx1 : wx0) * ((cc >> 1) ? wy1 : wy0);
            if (xi >= 0 && xi < WW && yi >= 0 && yi < HH)
                s += w * __half2float(vb[(size_t)(yi * WW + xi) * CC]);
        }
        acc += wsm[p] * s;
    }
    oh[(size_t)bq * CC + head * DH + di] = __float2half(acc);
}

// ---------------- launch ----------------
extern "C" void kernel_launch(void* const* d_in, const int* in_sizes, int n_in,
                              void* d_out, int out_size)
{
    const float* query = (const float*)d_in[0];
    const float* refp  = (const float*)d_in[1];
    const float* feat  = (const float*)d_in[2];
    int p = n_in - 18;
    const float* qn_g  = (const float*)d_in[p + 0];
    const float* qn_b  = (const float*)d_in[p + 1];
    const float* fn_g  = (const float*)d_in[p + 2];
    const float* fn_b  = (const float*)d_in[p + 3];
    const float* Wv    = (const float*)d_in[p + 4];
    const float* bv    = (const float*)d_in[p + 5];
    const float* Woff  = (const float*)d_in[p + 6];
    const float* boff  = (const float*)d_in[p + 7];
    const float* Watt  = (const float*)d_in[p + 8];
    const float* batt  = (const float*)d_in[p + 9];
    const float* Wout  = (const float*)d_in[p + 10];
    const float* bout  = (const float*)d_in[p + 11];
    const float* ffn_g = (const float*)d_in[p + 12];
    const float* ffn_b = (const float*)d_in[p + 13];
    const float* W1    = (const float*)d_in[p + 14];
    const float* b1    = (const float*)d_in[p + 15];
    const float* W2    = (const float*)d_in[p + 16];
    const float* b2    = (const float*)d_in[p + 17];
    float* out = (float*)d_out;

    __half *x, *val, *s, *hmid;
    __half *wvt, *wot, *wct, *w1t, *w2t;
    float *offatt, *bcomb, *b1p;
    cudaGetSymbolAddress((void**)&x, g_x);
    cudaGetSymbolAddress((void**)&val, g_value);
    cudaGetSymbolAddress((void**)&s, g_s);
    cudaGetSymbolAddress((void**)&hmid, g_hmid);
    cudaGetSymbolAddress((void**)&wvt, g_wvt);
    cudaGetSymbolAddress((void**)&wot, g_wot);
    cudaGetSymbolAddress((void**)&wct, g_wct);
    cudaGetSymbolAddress((void**)&w1t, g_w1t);
    cudaGetSymbolAddress((void**)&w2t, g_w2t);
    cudaGetSymbolAddress((void**)&offatt, g_offatt);
    cudaGetSymbolAddress((void**)&bcomb, g_bcomb);
    cudaGetSymbolAddress((void**)&b1p, g_b1p);

    const int SMEM_GEMM = 2 * 2 * 128 * SSTR * 2;   // 73728 B (2-stage)
    cudaFuncSetAttribute(mma_gemm<0>, cudaFuncAttributeMaxDynamicSharedMemorySize, SMEM_GEMM);
    cudaFuncSetAttribute(mma_gemm<1>, cudaFuncAttributeMaxDynamicSharedMemorySize, SMEM_GEMM);
    cudaFuncSetAttribute(mma_gemm<2>, cudaFuncAttributeMaxDynamicSharedMemorySize, SMEM_GEMM);
    cudaFuncSetAttribute(mma_gemm<3>, cudaFuncAttributeMaxDynamicSharedMemorySize, SMEM_GEMM);

    // weight prep (transpose to [Npad][K] fp16)
    wtrans_kernel<<<(CC*CC + 255)/256, 256>>>(Wv,   wvt, CC, CC, CC);
    wtrans_kernel<<<(CC*CC + 255)/256, 256>>>(Wout, wot, CC, CC, CC);
    wtrans_kernel<<<(96*CC + 255)/256, 256>>>(Woff, wct, CC, 96, 96);
    wtrans_kernel<<<(160*CC + 255)/256, 256>>>(Watt, wct + 96*CC, CC, 48, 160);
    wtrans_kernel<<<(256*CC + 255)/256, 256>>>(W1,  w1t, CC, HID, 256);
    wtrans_kernel<<<(CC*HID + 255)/256, 256>>>(W2,  w2t, HID, CC, CC);
    biasprep_kernel<<<1, 256>>>(boff, batt, b1, bcomb, b1p);

    // 1. value = LN(feat) @ Wv + bv  -> fp16
    ln_half_kernel<<<MROWS, 256>>>(feat, fn_g, fn_b, x);
    mma_gemm<3><<<dim3(6, 128), 256, SMEM_GEMM>>>(x, wvt, bv, nullptr,
        nullptr, val, CC, CC, CC);

    // 2. qn = LN(query); offsets + logits
    ln_half_kernel<<<MROWS, 256>>>(query, qn_g, qn_b, x);
    mma_gemm<0><<<dim3(2, 128), 256, SMEM_GEMM>>>(x, wct, bcomb, nullptr,
        offatt, nullptr, CC, 192, 144);

    // 3. softmax + bilinear sampling -> fp16
    sample_kernel<<<MROWS * NHH / 4, 256>>>(val, refp, offatt, s);

    // 4. out = query + samp @ Wout + bout
    mma_gemm<1><<<dim3(6, 128), 256, SMEM_GEMM>>>(s, wot, bout, query,
        out, nullptr, CC, CC, CC);

    // 5. FFN
    ln_half_kernel<<<MROWS, 256>>>(out, ffn_g, ffn_b, x);
    mma_gemm<2><<<dim3(2, 128), 256, SMEM_GEMM>>>(x, w1t, b1p, nullptr,
        nullptr, hmid, CC, HID, HID);
    mma_gemm<1><<<dim3(6, 128), 256, SMEM_GEMM>>>(hmid, w2t, b2, out,
        out, nullptr, HID, CC, CC);
}

// round 9
// speedup vs baseline: 3.9364x; 1.1304x over previous
#include <cuda_runtime.h>
#include <cuda_fp16.h>
#include <math.h>
#include <cstdint>

// Problem constants
#define B_    4
#define LQ    4096
#define CC    768
#define NHH   12
#define DH    64
#define HH    64
#define WW    64
#define HID   192
#define MROWS (B_*LQ)   // 16384

// ---------------- scratch ----------------
__device__ __align__(16) __half g_x[MROWS*CC];                      // LN output (fp16)
__device__ __align__(16) __half g_value[MROWS*CC];                  // value fp16 (gather src)
__device__ __align__(16) float  g_offatt[MROWS*192];                // off(96)+logits(48)+pad
__device__ __align__(16) __half g_s[MROWS*CC];                      // sampled fp16
__device__ __align__(16) __half g_hmid[MROWS*HID];                  // FFN hidden fp16
// transposed weights [Npad][K] fp16
__device__ __align__(16) __half g_wvt[CC*CC];
__device__ __align__(16) __half g_wot[CC*CC];
__device__ __align__(16) __half g_wct[256*CC];
__device__ __align__(16) __half g_w1t[256*CC];
__device__ __align__(16) __half g_w2t[CC*HID];
__device__ float g_bcomb[256], g_b1p[256];

// ---------------- fused weight prep: one launch ----------------
__global__ __launch_bounds__(256) void wprep_kernel(
    const float* Wv, const float* Wout, const float* Woff, const float* Watt,
    const float* W1, const float* W2,
    __half* wvt, __half* wot, __half* wct, __half* w1t, __half* w2t,
    const float* boff, const float* batt, const float* b1,
    float* bcomb, float* b1p)
{
    int blk = blockIdx.x;
    const float* src; __half* dst; int K, N, Npad, rel;
    if (blk < 2304)      { src=Wv;   dst=wvt;        K=CC;  N=CC;  Npad=CC;  rel=blk; }
    else if (blk < 4608) { src=Wout; dst=wot;        K=CC;  N=CC;  Npad=CC;  rel=blk-2304; }
    else if (blk < 4896) { src=Woff; dst=wct;        K=CC;  N=96;  Npad=96;  rel=blk-4608; }
    else if (blk < 5376) { src=Watt; dst=wct+96*CC;  K=CC;  N=48;  Npad=160; rel=blk-4896; }
    else if (blk < 6144) { src=W1;   dst=w1t;        K=CC;  N=HID; Npad=256; rel=blk-5376; }
    else if (blk < 6720) { src=W2;   dst=w2t;        K=HID; N=CC;  Npad=CC;  rel=blk-6144; }
    else {
        int i = threadIdx.x;
        bcomb[i] = (i < 96) ? boff[i] : (i < 144 ? batt[i - 96] : 0.0f);
        b1p[i]   = (i < 192) ? b1[i] : 0.0f;
        return;
    }
    int idx = rel * 256 + threadIdx.x;
    if (idx >= Npad * K) return;
    int n = idx / K, k = idx - n * K;
    float v = (n < N) ? src[(size_t)k * N + n] : 0.0f;
    dst[idx] = __float2half(v);
}

// ---------------- LayerNorm -> fp16 ----------------
__global__ __launch_bounds__(256) void ln_half_kernel(const float* __restrict__ in,
                                                      const float* __restrict__ gamma,
                                                      const float* __restrict__ beta,
                                                      __half* __restrict__ oh)
{
    int row = blockIdx.x;
    const float* x = in + (size_t)row * CC;
    int t = threadIdx.x;
    float v0 = x[t], v1 = x[t + 256], v2 = x[t + 512];
    float s  = v0 + v1 + v2;
    float s2 = v0*v0 + v1*v1 + v2*v2;
    #pragma unroll
    for (int o = 16; o; o >>= 1) {
        s  += __shfl_xor_sync(0xffffffffu, s,  o);
        s2 += __shfl_xor_sync(0xffffffffu, s2, o);
    }
    __shared__ float ssum[8], ssum2[8];
    int w = t >> 5;
    if ((t & 31) == 0) { ssum[w] = s; ssum2[w] = s2; }
    __syncthreads();
    float S = 0.f, S2 = 0.f;
    #pragma unroll
    for (int i = 0; i < 8; i++) { S += ssum[i]; S2 += ssum2[i]; }
    float mean = S * (1.0f / CC);
    float var  = S2 * (1.0f / CC) - mean * mean;
    float inv  = rsqrtf(var + 1e-5f);
    size_t base = (size_t)row * CC;
    #pragma unroll
    for (int i = 0; i < 3; i++) {
        int c = t + i * 256;
        float v = (i == 0 ? v0 : (i == 1 ? v1 : v2));
        oh[base + c] = __float2half((v - mean) * inv * gamma[c] + beta[c]);
    }
}

// ---------------- mma.sync fp16 GEMM, cp.async 3-stage, 1 sync/chunk ----------
// C[M,N] = A[M,K] @ B^T, B stored [Npad][K]. CTA 128x128, 8 warps 64x32, BK=64.
#define SSTR 72  // smem row stride in halfs

__device__ __forceinline__ void mma16816(float* d, const uint32_t* a, const uint32_t* b) {
    asm volatile(
        "mma.sync.aligned.m16n8k16.row.col.f32.f16.f16.f32 "
        "{%0,%1,%2,%3}, {%4,%5,%6,%7}, {%8,%9}, {%0,%1,%2,%3};"
        : "+f"(d[0]), "+f"(d[1]), "+f"(d[2]), "+f"(d[3])
        : "r"(a[0]), "r"(a[1]), "r"(a[2]), "r"(a[3]), "r"(b[0]), "r"(b[1]));
}
#define LDSM_X4(R0,R1,R2,R3,ADDR) \
    asm volatile("ldmatrix.sync.aligned.m8n8.x4.shared.b16 {%0,%1,%2,%3}, [%4];" \
        : "=r"(R0), "=r"(R1), "=r"(R2), "=r"(R3) : "r"(ADDR))
#define CPA16(DST,SRC) \
    asm volatile("cp.async.cg.shared.global [%0], [%1], 16;" :: "r"(DST), "l"(SRC) : "memory")
#define CPC() asm volatile("cp.async.commit_group;" ::: "memory")
#define CPW1() asm volatile("cp.async.wait_group 1;" ::: "memory")
#define CPW0() asm volatile("cp.async.wait_group 0;" ::: "memory")

// EPI: 0 bias->fp32; 1 bias+res->fp32; 2 bias+GELU->fp16; 3 bias->fp16
template<int EPI>
__global__ __launch_bounds__(256) void mma_gemm(
    const __half* __restrict__ A, const __half* __restrict__ B,
    const float* __restrict__ bias, const float* __restrict__ res,
    float* __restrict__ Cf, __half* __restrict__ Ch,
    int K, int ldc, int Ncols)
{
    extern __shared__ __half sm[];
    const int ARR = 128 * SSTR;        // halves per array
    const int STG = 2 * ARR;           // stage: A, B

    const int tid = threadIdx.x, lane = tid & 31, wid = tid >> 5;
    const int wm = wid & 1, wn = wid >> 1;           // warp grid 2x4
    const int m0 = blockIdx.y * 128, n0 = blockIdx.x * 128;

    const uint32_t smb = (uint32_t)__cvta_generic_to_shared(sm);

    int srow[4], sg[4];
    #pragma unroll
    for (int i = 0; i < 4; i++) { int idx = i * 256 + tid; srow[i] = idx >> 3; sg[i] = idx & 7; }

    auto issue = [&](int c, int s) {
        const int kc = c * 64;
        #pragma unroll
        for (int i = 0; i < 4; i++) {
            int row = srow[i], g = sg[i];
            size_t ga = (size_t)(m0 + row) * K + kc + g * 8;
            size_t gb = (size_t)(n0 + row) * K + kc + g * 8;
            uint32_t so = smb + (uint32_t)(s * STG + row * SSTR + g * 8) * 2;
            CPA16(so + 0 * ARR * 2, A + ga);
            CPA16(so + 1 * ARR * 2, B + gb);
        }
    };

    float acc[4][4][4];
    #pragma unroll
    for (int i = 0; i < 4; i++)
        #pragma unroll
        for (int j = 0; j < 4; j++)
            #pragma unroll
            for (int q = 0; q < 4; q++) acc[i][j][q] = 0.f;

    const int a_lrow = lane & 15, a_lcol = (lane >> 4) * 8;
    const int b_lrow = (lane & 7) + ((lane >> 4) * 8), b_lcol = ((lane >> 3) & 1) * 8;

    const int KC = K >> 6;   // always >= 3 here (K = 768 or 192)
    issue(0, 0); CPC();
    issue(1, 1); CPC();

    for (int c = 0; c < KC; c++) {
        // pending groups before wait: {c, c+1} (or {c} on last iter)
        if (c == KC - 1) { CPW0(); } else { CPW1(); }   // chunk c landed
        __syncthreads();   // all warps see stage c%3; also orders reads of stage (c+2)%3 from iter c-1
        if (c + 2 < KC) { issue(c + 2, (c + 2) % 3); CPC(); }

        const int st = (c % 3) * STG;
        const uint32_t baseA = smb + (uint32_t)(st + 0 * ARR) * 2;
        const uint32_t baseB = smb + (uint32_t)(st + 1 * ARR) * 2;

        #pragma unroll
        for (int kk = 0; kk < 4; kk++) {
            const int kb = kk * 16;
            uint32_t bf[4][2];
            #pragma unroll
            for (int nn = 0; nn < 2; nn++) {
                uint32_t off = (uint32_t)((wn * 32 + nn * 16 + b_lrow) * SSTR + kb + b_lcol) * 2;
                LDSM_X4(bf[nn*2][0], bf[nn*2][1], bf[nn*2+1][0], bf[nn*2+1][1], baseB + off);
            }
            #pragma unroll
            for (int mi = 0; mi < 4; mi++) {
                uint32_t off = (uint32_t)((wm * 64 + mi * 16 + a_lrow) * SSTR + kb + a_lcol) * 2;
                uint32_t ah[4];
                LDSM_X4(ah[0], ah[1], ah[2], ah[3], baseA + off);
                #pragma unroll
                for (int ni = 0; ni < 4; ni++)
                    mma16816(acc[mi][ni], ah, bf[ni]);
            }
        }
    }

    // ---- epilogue (adjacent-column float2/half2 stores) ----
    const int qrow = lane >> 2, qk = (lane & 3) * 2;
    #pragma unroll
    for (int mi = 0; mi < 4; mi++) {
        #pragma unroll
        for (int ni = 0; ni < 4; ni++) {
            int c0 = n0 + wn * 32 + ni * 8 + qk;
            if (c0 >= Ncols) continue;
            int r0 = m0 + wm * 64 + mi * 16 + qrow;
            float b0 = bias[c0], b1v = bias[c0 + 1];
            #pragma unroll
            for (int h = 0; h < 2; h++) {
                int m = r0 + h * 8;
                float v0 = acc[mi][ni][h*2+0] + b0;
                float v1 = acc[mi][ni][h*2+1] + b1v;
                if (EPI == 1) {
                    float2 rr = *reinterpret_cast<const float2*>(res + (size_t)m * ldc + c0);
                    v0 += rr.x; v1 += rr.y;
                }
                if (EPI == 2) {
                    v0 = 0.5f * v0 * (1.0f + erff(v0 * 0.70710678118654752f));
                    v1 = 0.5f * v1 * (1.0f + erff(v1 * 0.70710678118654752f));
                }
                if (EPI == 2 || EPI == 3) {
                    *reinterpret_cast<__half2*>(Ch + (size_t)m * ldc + c0) =
                        __floats2half2_rn(v0, v1);
                } else {
                    *reinterpret_cast<float2*>(Cf + (size_t)m * ldc + c0) =
                        make_float2(v0, v1);
                }
            }
        }
    }
}

// ---------------- sampling: softmax(4) + bilinear -> fp16 ----------------
__global__ __launch_bounds__(256) void sample_kernel(
    const __half* __restrict__ value,   // [B, HW, 768] fp16
    const float* __restrict__ refp,     // [B, Lq, 1, 2]
    const float* __restrict__ offatt,   // [B*Lq, 192]
    __half* __restrict__ oh)
{
    int gid = blockIdx.x * 4 + (threadIdx.x >> 6);
    int di  = threadIdx.x & 63;
    int head = gid % NHH;
    int bq   = gid / NHH;
    int b    = bq / LQ;

    const float* rp = refp + (size_t)bq * 2;
    float rx = rp[0], ry = rp[1];
    const float* op = offatt + (size_t)bq * 192 + head * 8;
    const float* lp = offatt + (size_t)bq * 192 + 96 + head * 4;

    float l0 = lp[0], l1 = lp[1], l2 = lp[2], l3 = lp[3];
    float mx = fmaxf(fmaxf(l0, l1), fmaxf(l2, l3));
    float e0 = expf(l0 - mx), e1 = expf(l1 - mx), e2 = expf(l2 - mx), e3 = expf(l3 - mx);
    float inv = 1.0f / (e0 + e1 + e2 + e3);
    float wsm[4] = {e0 * inv, e1 * inv, e2 * inv, e3 * inv};

    const __half* vb = value + (size_t)b * (HH * WW) * CC + head * DH + di;
    float acc = 0.f;
    #pragma unroll
    for (int p = 0; p < 4; p++) {
        float x = rx * (float)WW + op[p*2+0] - 0.5f;
        float y = ry * (float)HH + op[p*2+1] - 0.5f;
        float x0f = floorf(x), y0f = floorf(y);
        int   x0 = (int)x0f,  y0 = (int)y0f;
        float wx1 = x - x0f, wy1 = y - y0f;
        float wx0 = 1.f - wx1, wy0 = 1.f - wy1;
        float s = 0.f;
        #pragma unroll
        for (int cc = 0; cc < 4; cc++) {
            int xi = x0 + (cc & 1);
            int yi = y0 + (cc >> 1);
            float w = ((cc & 1) ? wx1 : wx0) * ((cc >> 1) ? wy1 : wy0);
            if (xi >= 0 && xi < WW && yi >= 0 && yi < HH)
                s += w * __half2float(vb[(size_t)(yi * WW + xi) * CC]);
        }
        acc += wsm[p] * s;
    }
    oh[(size_t)bq * CC + head * DH + di] = __float2half(acc);
}

// ---------------- launch ----------------
extern "C" void kernel_launch(void* const* d_in, const int* in_sizes, int n_in,
                              void* d_out, int out_size)
{
    const float* query = (const float*)d_in[0];
    const float* refp  = (const float*)d_in[1];
    const float* feat  = (const float*)d_in[2];
    int p = n_in - 18;
    const float* qn_g  = (const float*)d_in[p + 0];
    const float* qn_b  = (const float*)d_in[p + 1];
    const float* fn_g  = (const float*)d_in[p + 2];
    const float* fn_b  = (const float*)d_in[p + 3];
    const float* Wv    = (const float*)d_in[p + 4];
    const float* bv    = (const float*)d_in[p + 5];
    const float* Woff  = (const float*)d_in[p + 6];
    const float* boff  = (const float*)d_in[p + 7];
    const float* Watt  = (const float*)d_in[p + 8];
    const float* batt  = (const float*)d_in[p + 9];
    const float* Wout  = (const float*)d_in[p + 10];
    const float* bout  = (const float*)d_in[p + 11];
    const float* ffn_g = (const float*)d_in[p + 12];
    const float* ffn_b = (const float*)d_in[p + 13];
    const float* W1    = (const float*)d_in[p + 14];
    const float* b1    = (const float*)d_in[p + 15];
    const float* W2    = (const float*)d_in[p + 16];
    const float* b2    = (const float*)d_in[p + 17];
    float* out = (float*)d_out;

    __half *x, *val, *s, *hmid;
    __half *wvt, *wot, *wct, *w1t, *w2t;
    float *offatt, *bcomb, *b1p;
    cudaGetSymbolAddress((void**)&x, g_x);
    cudaGetSymbolAddress((void**)&val, g_value);
    cudaGetSymbolAddress((void**)&s, g_s);
    cudaGetSymbolAddress((void**)&hmid, g_hmid);
    cudaGetSymbolAddress((void**)&wvt, g_wvt);
    cudaGetSymbolAddress((void**)&wot, g_wot);
    cudaGetSymbolAddress((void**)&wct, g_wct);
    cudaGetSymbolAddress((void**)&w1t, g_w1t);
    cudaGetSymbolAddress((void**)&w2t, g_w2t);
    cudaGetSymbolAddress((void**)&offatt, g_offatt);
    cudaGetSymbolAddress((void**)&bcomb, g_bcomb);
    cudaGetSymbolAddress((void**)&b1p, g_b1p);

    const int SMEM_GEMM = 3 * 2 * 128 * SSTR * 2;   // 110592 B (3-stage) -> 2 CTAs/SM
    cudaFuncSetAttribute(mma_gemm<0>, cudaFuncAttributeMaxDynamicSharedMemorySize, SMEM_GEMM);
    cudaFuncSetAttribute(mma_gemm<1>, cudaFuncAttributeMaxDynamicSharedMemorySize, SMEM_GEMM);
    cudaFuncSetAttribute(mma_gemm<2>, cudaFuncAttributeMaxDynamicSharedMemorySize, SMEM_GEMM);
    cudaFuncSetAttribute(mma_gemm<3>, cudaFuncAttributeMaxDynamicSharedMemorySize, SMEM_GEMM);

    // fused weight prep (single launch)
    wprep_kernel<<<6721, 256>>>(Wv, Wout, Woff, Watt, W1, W2,
        wvt, wot, wct, w1t, w2t, boff, batt, b1, bcomb, b1p);

    // 1. value = LN(feat) @ Wv + bv  -> fp16
    ln_half_kernel<<<MROWS, 256>>>(feat, fn_g, fn_b, x);
    mma_gemm<3><<<dim3(6, 128), 256, SMEM_GEMM>>>(x, wvt, bv, nullptr,
        nullptr, val, CC, CC, CC);

    // 2. qn = LN(query); offsets + logits
    ln_half_kernel<<<MROWS, 256>>>(query, qn_g, qn_b, x);
    mma_gemm<0><<<dim3(2, 128), 256, SMEM_GEMM>>>(x, wct, bcomb, nullptr,
        offatt, nullptr, CC, 192, 144);

    // 3. softmax + bilinear sampling -> fp16
    sample_kernel<<<MROWS * NHH / 4, 256>>>(val, refp, offatt, s);

    // 4. out = query + samp @ Wout + bout
    mma_gemm<1><<<dim3(6, 128), 256, SMEM_GEMM>>>(s, wot, bout, query,
        out, nullptr, CC, CC, CC);

    // 5. FFN
    ln_half_kernel<<<MROWS, 256>>>(out, ffn_g, ffn_b, x);
    mma_gemm<2><<<dim3(2, 128), 256, SMEM_GEMM>>>(x, w1t, b1p, nullptr,
        nullptr, hmid, CC, HID, HID);
    mma_gemm<1><<<dim3(6, 128), 256, SMEM_GEMM>>>(hmid, w2t, b2, out,
        out, nullptr, HID, CC, CC);
}

// round 10
// speedup vs baseline: 4.0058x; 1.0176x over previous
#include <cuda_runtime.h>
#include <cuda_fp16.h>
#include <math.h>
#include <cstdint>

// Problem constants
#define B_    4
#define LQ    4096
#define CC    768
#define NHH   12
#define DH    64
#define HH    64
#define WW    64
#define HID   192
#define MROWS (B_*LQ)   // 16384

// ---------------- scratch ----------------
__device__ __align__(16) __half g_xf[MROWS*CC];                     // LN(feat) fp16
__device__ __align__(16) __half g_xq[MROWS*CC];                     // LN(query) fp16
__device__ __align__(16) __half g_value[MROWS*CC];                  // value fp16
__device__ __align__(16) float  g_offatt[MROWS*192];                // off(96)+logits(48)+pad
__device__ __align__(16) __half g_s[MROWS*CC];                      // sampled fp16
__device__ __align__(16) __half g_hmid[MROWS*HID];                  // FFN hidden fp16
// transposed weights [Npad][K] fp16
__device__ __align__(16) __half g_wvt[CC*CC];
__device__ __align__(16) __half g_wot[CC*CC];
__device__ __align__(16) __half g_wct[256*CC];
__device__ __align__(16) __half g_w1t[256*CC];
__device__ __align__(16) __half g_w2t[CC*HID];
__device__ float g_bcomb[256], g_b1p[256];

// ---------------- vectorized LN body (256 thr, 192 active lanes of float4) ----
__device__ __forceinline__ void ln_row(const float* __restrict__ in,
                                       const float* __restrict__ gamma,
                                       const float* __restrict__ beta,
                                       __half* __restrict__ oh, int row)
{
    int t = threadIdx.x;
    float4 v = make_float4(0.f, 0.f, 0.f, 0.f);
    if (t < 192) v = *reinterpret_cast<const float4*>(in + (size_t)row * CC + t * 4);
    float s  = v.x + v.y + v.z + v.w;
    float s2 = v.x*v.x + v.y*v.y + v.z*v.z + v.w*v.w;
    #pragma unroll
    for (int o = 16; o; o >>= 1) {
        s  += __shfl_xor_sync(0xffffffffu, s,  o);
        s2 += __shfl_xor_sync(0xffffffffu, s2, o);
    }
    __shared__ float ssum[8], ssum2[8];
    int w = t >> 5;
    if ((t & 31) == 0) { ssum[w] = s; ssum2[w] = s2; }
    __syncthreads();
    float S = 0.f, S2 = 0.f;
    #pragma unroll
    for (int i = 0; i < 8; i++) { S += ssum[i]; S2 += ssum2[i]; }
    float mean = S * (1.0f / CC);
    float var  = S2 * (1.0f / CC) - mean * mean;
    float inv  = rsqrtf(var + 1e-5f);
    if (t < 192) {
        float4 gg = *reinterpret_cast<const float4*>(gamma + t * 4);
        float4 bb = *reinterpret_cast<const float4*>(beta  + t * 4);
        __half2 h0 = __floats2half2_rn((v.x - mean) * inv * gg.x + bb.x,
                                       (v.y - mean) * inv * gg.y + bb.y);
        __half2 h1 = __floats2half2_rn((v.z - mean) * inv * gg.z + bb.z,
                                       (v.w - mean) * inv * gg.w + bb.w);
        *reinterpret_cast<__half2*>(oh + (size_t)row * CC + t * 4)     = h0;
        *reinterpret_cast<__half2*>(oh + (size_t)row * CC + t * 4 + 2) = h1;
    }
}

// ---------------- fused prep: weight transpose + both LNs, ONE launch ----------
__global__ __launch_bounds__(256) void prep_kernel(
    const float* __restrict__ feat, const float* __restrict__ query,
    const float* __restrict__ fn_g, const float* __restrict__ fn_b,
    const float* __restrict__ qn_g, const float* __restrict__ qn_b,
    __half* __restrict__ xf, __half* __restrict__ xq,
    const float* Wv, const float* Wout, const float* Woff, const float* Watt,
    const float* W1, const float* W2,
    __half* wvt, __half* wot, __half* wct, __half* w1t, __half* w2t,
    const float* boff, const float* batt, const float* b1,
    float* bcomb, float* b1p)
{
    int blk = blockIdx.x;
    if (blk >= 6721) {
        int row = blk - 6721;
        if (row < MROWS) ln_row(feat, fn_g, fn_b, xf, row);
        else             ln_row(query, qn_g, qn_b, xq, row - MROWS);
        return;
    }
    const float* src; __half* dst; int K, N, Npad, rel;
    if (blk < 2304)      { src=Wv;   dst=wvt;        K=CC;  N=CC;  Npad=CC;  rel=blk; }
    else if (blk < 4608) { src=Wout; dst=wot;        K=CC;  N=CC;  Npad=CC;  rel=blk-2304; }
    else if (blk < 4896) { src=Woff; dst=wct;        K=CC;  N=96;  Npad=96;  rel=blk-4608; }
    else if (blk < 5376) { src=Watt; dst=wct+96*CC;  K=CC;  N=48;  Npad=160; rel=blk-4896; }
    else if (blk < 6144) { src=W1;   dst=w1t;        K=CC;  N=HID; Npad=256; rel=blk-5376; }
    else if (blk < 6720) { src=W2;   dst=w2t;        K=HID; N=CC;  Npad=CC;  rel=blk-6144; }
    else {
        int i = threadIdx.x;
        bcomb[i] = (i < 96) ? boff[i] : (i < 144 ? batt[i - 96] : 0.0f);
        b1p[i]   = (i < 192) ? b1[i] : 0.0f;
        return;
    }
    int idx = rel * 256 + threadIdx.x;
    if (idx >= Npad * K) return;
    int n = idx / K, k = idx - n * K;
    float v = (n < N) ? src[(size_t)k * N + n] : 0.0f;
    dst[idx] = __float2half(v);
}

// ---------------- LN-only kernel (FFN norm) ----------------
__global__ __launch_bounds__(256) void ln_kernel(const float* __restrict__ in,
                                                 const float* __restrict__ gamma,
                                                 const float* __restrict__ beta,
                                                 __half* __restrict__ oh)
{
    ln_row(in, gamma, beta, oh, blockIdx.x);
}

// ---------------- GEMM core (shared device body) ----------------
#define SSTR 72  // smem row stride in halfs

__device__ __forceinline__ void mma16816(float* d, const uint32_t* a, const uint32_t* b) {
    asm volatile(
        "mma.sync.aligned.m16n8k16.row.col.f32.f16.f16.f32 "
        "{%0,%1,%2,%3}, {%4,%5,%6,%7}, {%8,%9}, {%0,%1,%2,%3};"
        : "+f"(d[0]), "+f"(d[1]), "+f"(d[2]), "+f"(d[3])
        : "r"(a[0]), "r"(a[1]), "r"(a[2]), "r"(a[3]), "r"(b[0]), "r"(b[1]));
}
#define LDSM_X4(R0,R1,R2,R3,ADDR) \
    asm volatile("ldmatrix.sync.aligned.m8n8.x4.shared.b16 {%0,%1,%2,%3}, [%4];" \
        : "=r"(R0), "=r"(R1), "=r"(R2), "=r"(R3) : "r"(ADDR))
#define CPA16(DST,SRC) \
    asm volatile("cp.async.cg.shared.global [%0], [%1], 16;" :: "r"(DST), "l"(SRC) : "memory")
#define CPC() asm volatile("cp.async.commit_group;" ::: "memory")
#define CPW1() asm volatile("cp.async.wait_group 1;" ::: "memory")
#define CPW0() asm volatile("cp.async.wait_group 0;" ::: "memory")

// EPI: 0 bias->fp32; 1 bias+res->fp32; 2 bias+GELU->fp16; 3 bias->fp16
template<int EPI>
__device__ __forceinline__ void gemm_body(
    const __half* __restrict__ A, const __half* __restrict__ B,
    const float* __restrict__ bias, const float* __restrict__ res,
    float* __restrict__ Cf, __half* __restrict__ Ch,
    int K, int ldc, int Ncols, int m0, int n0, __half* sm)
{
    const int ARR = 128 * SSTR;
    const int STG = 2 * ARR;

    const int tid = threadIdx.x, lane = tid & 31, wid = tid >> 5;
    const int wm = wid & 1, wn = wid >> 1;

    const uint32_t smb = (uint32_t)__cvta_generic_to_shared(sm);

    int srow[4], sg[4];
    #pragma unroll
    for (int i = 0; i < 4; i++) { int idx = i * 256 + tid; srow[i] = idx >> 3; sg[i] = idx & 7; }

    auto issue = [&](int c, int s) {
        const int kc = c * 64;
        #pragma unroll
        for (int i = 0; i < 4; i++) {
            int row = srow[i], g = sg[i];
            size_t ga = (size_t)(m0 + row) * K + kc + g * 8;
            size_t gb = (size_t)(n0 + row) * K + kc + g * 8;
            uint32_t so = smb + (uint32_t)(s * STG + row * SSTR + g * 8) * 2;
            CPA16(so + 0 * ARR * 2, A + ga);
            CPA16(so + 1 * ARR * 2, B + gb);
        }
    };

    float acc[4][4][4];
    #pragma unroll
    for (int i = 0; i < 4; i++)
        #pragma unroll
        for (int j = 0; j < 4; j++)
            #pragma unroll
            for (int q = 0; q < 4; q++) acc[i][j][q] = 0.f;

    const int a_lrow = lane & 15, a_lcol = (lane >> 4) * 8;
    const int b_lrow = (lane & 7) + ((lane >> 4) * 8), b_lcol = ((lane >> 3) & 1) * 8;

    const int KC = K >> 6;
    issue(0, 0); CPC();
    issue(1, 1); CPC();

    for (int c = 0; c < KC; c++) {
        if (c == KC - 1) { CPW0(); } else { CPW1(); }
        __syncthreads();
        if (c + 2 < KC) { issue(c + 2, (c + 2) % 3); CPC(); }

        const int st = (c % 3) * STG;
        const uint32_t baseA = smb + (uint32_t)(st + 0 * ARR) * 2;
        const uint32_t baseB = smb + (uint32_t)(st + 1 * ARR) * 2;

        #pragma unroll
        for (int kk = 0; kk < 4; kk++) {
            const int kb = kk * 16;
            uint32_t bf[4][2];
            #pragma unroll
            for (int nn = 0; nn < 2; nn++) {
                uint32_t off = (uint32_t)((wn * 32 + nn * 16 + b_lrow) * SSTR + kb + b_lcol) * 2;
                LDSM_X4(bf[nn*2][0], bf[nn*2][1], bf[nn*2+1][0], bf[nn*2+1][1], baseB + off);
            }
            #pragma unroll
            for (int mi = 0; mi < 4; mi++) {
                uint32_t off = (uint32_t)((wm * 64 + mi * 16 + a_lrow) * SSTR + kb + a_lcol) * 2;
                uint32_t ah[4];
                LDSM_X4(ah[0], ah[1], ah[2], ah[3], baseA + off);
                #pragma unroll
                for (int ni = 0; ni < 4; ni++)
                    mma16816(acc[mi][ni], ah, bf[ni]);
            }
        }
    }

    const int qrow = lane >> 2, qk = (lane & 3) * 2;
    #pragma unroll
    for (int mi = 0; mi < 4; mi++) {
        #pragma unroll
        for (int ni = 0; ni < 4; ni++) {
            int c0 = n0 + wn * 32 + ni * 8 + qk;
            if (c0 >= Ncols) continue;
            int r0 = m0 + wm * 64 + mi * 16 + qrow;
            float b0 = bias[c0], b1v = bias[c0 + 1];
            #pragma unroll
            for (int h = 0; h < 2; h++) {
                int m = r0 + h * 8;
                float v0 = acc[mi][ni][h*2+0] + b0;
                float v1 = acc[mi][ni][h*2+1] + b1v;
                if (EPI == 1) {
                    float2 rr = *reinterpret_cast<const float2*>(res + (size_t)m * ldc + c0);
                    v0 += rr.x; v1 += rr.y;
                }
                if (EPI == 2) {
                    v0 = 0.5f * v0 * (1.0f + erff(v0 * 0.70710678118654752f));
                    v1 = 0.5f * v1 * (1.0f + erff(v1 * 0.70710678118654752f));
                }
                if (EPI == 2 || EPI == 3) {
                    *reinterpret_cast<__half2*>(Ch + (size_t)m * ldc + c0) =
                        __floats2half2_rn(v0, v1);
                } else {
                    *reinterpret_cast<float2*>(Cf + (size_t)m * ldc + c0) =
                        make_float2(v0, v1);
                }
            }
        }
    }
}

// standalone GEMM kernel
template<int EPI>
__global__ __launch_bounds__(256) void mma_gemm(
    const __half* __restrict__ A, const __half* __restrict__ B,
    const float* __restrict__ bias, const float* __restrict__ res,
    float* __restrict__ Cf, __half* __restrict__ Ch,
    int K, int ldc, int Ncols)
{
    extern __shared__ __half sm[];
    gemm_body<EPI>(A, B, bias, res, Cf, Ch, K, ldc, Ncols,
                   blockIdx.y * 128, blockIdx.x * 128, sm);
}

// fused pair: value GEMM (768 CTAs) + offset/attention GEMM (256 CTAs)
__global__ __launch_bounds__(256) void gemm_pair_kernel(
    const __half* __restrict__ xf, const __half* __restrict__ wvt,
    const float* __restrict__ bv, __half* __restrict__ val,
    const __half* __restrict__ xq, const __half* __restrict__ wct,
    const float* __restrict__ bcomb, float* __restrict__ offatt)
{
    extern __shared__ __half sm[];
    int t = blockIdx.x;
    if (t < 768) {
        gemm_body<3>(xf, wvt, bv, nullptr, nullptr, val,
                     CC, CC, CC, (t / 6) * 128, (t % 6) * 128, sm);
    } else {
        int t2 = t - 768;
        gemm_body<0>(xq, wct, bcomb, nullptr, offatt, nullptr,
                     CC, 192, 144, (t2 / 2) * 128, (t2 % 2) * 128, sm);
    }
}

// ---------------- sampling: softmax(4) + bilinear -> fp16 ----------------
__global__ __launch_bounds__(256) void sample_kernel(
    const __half* __restrict__ value,
    const float* __restrict__ refp,
    const float* __restrict__ offatt,
    __half* __restrict__ oh)
{
    int gid = blockIdx.x * 4 + (threadIdx.x >> 6);
    int di  = threadIdx.x & 63;
    int head = gid % NHH;
    int bq   = gid / NHH;
    int b    = bq / LQ;

    const float* rp = refp + (size_t)bq * 2;
    float rx = rp[0], ry = rp[1];
    const float* op = offatt + (size_t)bq * 192 + head * 8;
    const float* lp = offatt + (size_t)bq * 192 + 96 + head * 4;

    float l0 = lp[0], l1 = lp[1], l2 = lp[2], l3 = lp[3];
    float mx = fmaxf(fmaxf(l0, l1), fmaxf(l2, l3));
    float e0 = expf(l0 - mx), e1 = expf(l1 - mx), e2 = expf(l2 - mx), e3 = expf(l3 - mx);
    float inv = 1.0f / (e0 + e1 + e2 + e3);
    float wsm[4] = {e0 * inv, e1 * inv, e2 * inv, e3 * inv};

    const __half* vb = value + (size_t)b * (HH * WW) * CC + head * DH + di;
    float acc = 0.f;
    #pragma unroll
    for (int p = 0; p < 4; p++) {
        float x = rx * (float)WW + op[p*2+0] - 0.5f;
        float y = ry * (float)HH + op[p*2+1] - 0.5f;
        float x0f = floorf(x), y0f = floorf(y);
        int   x0 = (int)x0f,  y0 = (int)y0f;
        float wx1 = x - x0f, wy1 = y - y0f;
        float wx0 = 1.f - wx1, wy0 = 1.f - wy1;
        float s = 0.f;
        #pragma unroll
        for (int cc = 0; cc < 4; cc++) {
            int xi = x0 + (cc & 1);
            int yi = y0 + (cc >> 1);
            float w = ((cc & 1) ? wx1 : wx0) * ((cc >> 1) ? wy1 : wy0);
            if (xi >= 0 && xi < WW && yi >= 0 && yi < HH)
                s += w * __half2float(vb[(size_t)(yi * WW + xi) * CC]);
        }
        acc += wsm[p] * s;
    }
    oh[(size_t)bq * CC + head * DH + di] = __float2half(acc);
}

// ---------------- launch ----------------
extern "C" void kernel_launch(void* const* d_in, const int* in_sizes, int n_in,
                              void* d_out, int out_size)
{
    const float* query = (const float*)d_in[0];
    const float* refp  = (const float*)d_in[1];
    const float* feat  = (const float*)d_in[2];
    int p = n_in - 18;
    const float* qn_g  = (const float*)d_in[p + 0];
    const float* qn_b  = (const float*)d_in[p + 1];
    const float* fn_g  = (const float*)d_in[p + 2];
    const float* fn_b  = (const float*)d_in[p + 3];
    const float* Wv    = (const float*)d_in[p + 4];
    const float* bv    = (const float*)d_in[p + 5];
    const float* Woff  = (const float*)d_in[p + 6];
    const float* boff  = (const float*)d_in[p + 7];
    const float* Watt  = (const float*)d_in[p + 8];
    const float* batt  = (const float*)d_in[p + 9];
    const float* Wout  = (const float*)d_in[p + 10];
    const float* bout  = (const float*)d_in[p + 11];
    const float* ffn_g = (const float*)d_in[p + 12];
    const float* ffn_b = (const float*)d_in[p + 13];
    const float* W1    = (const float*)d_in[p + 14];
    const float* b1    = (const float*)d_in[p + 15];
    const float* W2    = (const float*)d_in[p + 16];
    const float* b2    = (const float*)d_in[p + 17];
    float* out = (float*)d_out;

    __half *xf, *xq, *val, *s, *hmid;
    __half *wvt, *wot, *wct, *w1t, *w2t;
    float *offatt, *bcomb, *b1p;
    cudaGetSymbolAddress((void**)&xf, g_xf);
    cudaGetSymbolAddress((void**)&xq, g_xq);
    cudaGetSymbolAddress((void**)&val, g_value);
    cudaGetSymbolAddress((void**)&s, g_s);
    cudaGetSymbolAddress((void**)&hmid, g_hmid);
    cudaGetSymbolAddress((void**)&wvt, g_wvt);
    cudaGetSymbolAddress((void**)&wot, g_wot);
    cudaGetSymbolAddress((void**)&wct, g_wct);
    cudaGetSymbolAddress((void**)&w1t, g_w1t);
    cudaGetSymbolAddress((void**)&w2t, g_w2t);
    cudaGetSymbolAddress((void**)&offatt, g_offatt);
    cudaGetSymbolAddress((void**)&bcomb, g_bcomb);
    cudaGetSymbolAddress((void**)&b1p, g_b1p);

    const int SMEM_GEMM = 3 * 2 * 128 * SSTR * 2;   // 110592 B
    cudaFuncSetAttribute(mma_gemm<1>, cudaFuncAttributeMaxDynamicSharedMemorySize, SMEM_GEMM);
    cudaFuncSetAttribute(mma_gemm<2>, cudaFuncAttributeMaxDynamicSharedMemorySize, SMEM_GEMM);
    cudaFuncSetAttribute(gemm_pair_kernel, cudaFuncAttributeMaxDynamicSharedMemorySize, SMEM_GEMM);

    // 1. fused prep: weight transpose + LN(feat) + LN(query)
    prep_kernel<<<6721 + 2 * MROWS, 256>>>(feat, query, fn_g, fn_b, qn_g, qn_b, xf, xq,
        Wv, Wout, Woff, Watt, W1, W2, wvt, wot, wct, w1t, w2t,
        boff, batt, b1, bcomb, b1p);

    // 2. fused GEMM pair: value + offsets/logits
    gemm_pair_kernel<<<1024, 256, SMEM_GEMM>>>(xf, wvt, bv, val, xq, wct, bcomb, offatt);

    // 3. softmax + bilinear sampling -> fp16
    sample_kernel<<<MROWS * NHH / 4, 256>>>(val, refp, offatt, s);

    // 4. out = query + samp @ Wout + bout
    mma_gemm<1><<<dim3(6, 128), 256, SMEM_GEMM>>>(s, wot, bout, query,
        out, nullptr, CC, CC, CC);

    // 5. FFN
    ln_kernel<<<MROWS, 256>>>(out, ffn_g, ffn_b, xf);
    mma_gemm<2><<<dim3(2, 128), 256, SMEM_GEMM>>>(xf, w1t, b1p, nullptr,
        nullptr, hmid, CC, HID, HID);
    mma_gemm<1><<<dim3(6, 128), 256, SMEM_GEMM>>>(hmid, w2t, b2, out,
        out, nullptr, HID, CC, CC);
}